// round 5
// baseline (speedup 1.0000x reference)
#include <cuda_runtime.h>
#include <mma.h>
#include <cstdint>

using namespace nvcuda;

#define SQ   512
#define BB   4
#define DIN_ 768
#define DD   1024
#define HH   16
#define HDIM 64
#define FF_  4096
#define MROWS 2048   // S*B
#define LAYERS 12

// ---------------- device scratch (no allocs allowed) ----------------
__device__ float g_x   [MROWS*DD];
__device__ float g_h   [MROWS*DD];
__device__ float g_q   [MROWS*DD];
__device__ float g_k   [MROWS*DD];
__device__ float g_v   [MROWS*DD];
__device__ float g_attn[MROWS*DD];
__device__ float g_ffh [MROWS*FF_];
__device__ float g_scores[(size_t)BB*HH*SQ*SQ];
__device__ float g_rope[SQ*32*2];   // interleaved cos,sin per (s, j<32)
__device__ int   g_mask[BB*SQ];     // canonical 0/1 key mask

// ---------------- mask canonicalization (bool / int32 / float32 robust) ----
__global__ void k_mask_prep(const unsigned char* __restrict__ raw,
                            int* __restrict__ outm){
    __shared__ int s_float, s_bool;
    if (threadIdx.x==0){ s_float=0; s_bool=0; }
    __syncthreads();
    // Scan only the first 2048 bytes (safe under every candidate layout).
    for (int i=threadIdx.x; i<BB*SQ; i+=256){
        unsigned char v = raw[i];
        if ((i&3)==3 && v==0x3f) atomicOr(&s_float,1);   // 1.0f byte pattern
        else if ((i&3)!=0 && v!=0) atomicOr(&s_bool,1);  // random bools
    }
    __syncthreads();
    int mode = s_float ? 2 : (s_bool ? 0 : 1); // 0=bool, 1=int32, 2=float32
    for (int i=threadIdx.x; i<BB*SQ; i+=256){
        int m;
        if (mode==0)      m = raw[i] != 0;
        else if (mode==1) m = ((const int*)raw)[i] != 0;
        else              m = ((const float*)raw)[i] != 0.f;
        outm[i] = m;
    }
}

// ---------------- RoPE cache ----------------
__global__ void k_rope_cache(float* __restrict__ cache){
    int i = blockIdx.x*blockDim.x + threadIdx.x;
    if (i >= SQ*32) return;
    int s = i >> 5, j = i & 31;
    float invf = powf(10000.f, -((float)(2*j)) / 64.f);
    float a = (float)s * invf;
    cache[2*i]   = cosf(a);
    cache[2*i+1] = sinf(a);
}

__global__ __launch_bounds__(256) void k_rope_apply(float* __restrict__ q,
                                                    float* __restrict__ k,
                                                    const float* __restrict__ cache){
    int i = blockIdx.x*256 + threadIdx.x;        // < 2048*16*32
    int j = i & 31;
    int h = (i >> 5) & 15;
    int r = i >> 9;                               // row = s*B+b
    int s = r >> 2;                               // B=4
    float c  = cache[(s*32+j)*2];
    float sn = cache[(s*32+j)*2+1];
    size_t base = (size_t)r*DD + h*HDIM;
    float a1 = q[base+j], a2 = q[base+j+32];
    q[base+j]    = a1*c - a2*sn;
    q[base+j+32] = a2*c + a1*sn;
    float b1 = k[base+j], b2 = k[base+j+32];
    k[base+j]    = b1*c - b2*sn;
    k[base+j+32] = b2*c + b1*sn;
}

// ---------------- LayerNorm ----------------
__global__ __launch_bounds__(256) void k_ln(const float* __restrict__ x,
                                            const float* __restrict__ g,
                                            const float* __restrict__ b,
                                            float* __restrict__ out){
    int row = blockIdx.x, tid = threadIdx.x;
    const float4* xr = (const float4*)(x + (size_t)row*DD);
    float4 v = xr[tid];
    float s  = v.x+v.y+v.z+v.w;
    float q2 = v.x*v.x+v.y*v.y+v.z*v.z+v.w*v.w;
    #pragma unroll
    for (int o=16;o;o>>=1){ s += __shfl_xor_sync(0xffffffffu,s,o);
                            q2 += __shfl_xor_sync(0xffffffffu,q2,o); }
    __shared__ float ss[8], sq[8];
    if ((tid&31)==0){ ss[tid>>5]=s; sq[tid>>5]=q2; }
    __syncthreads();
    float S_=0.f, Q_=0.f;
    #pragma unroll
    for (int i=0;i<8;i++){ S_+=ss[i]; Q_+=sq[i]; }
    float mean = S_ * (1.f/DD);
    float var  = Q_ * (1.f/DD) - mean*mean;
    float inv  = rsqrtf(var + 1e-5f);
    float4 gg = ((const float4*)g)[tid];
    float4 bb = ((const float4*)b)[tid];
    float4 o4;
    o4.x = (v.x-mean)*inv*gg.x + bb.x;
    o4.y = (v.y-mean)*inv*gg.y + bb.y;
    o4.z = (v.z-mean)*inv*gg.z + bb.z;
    o4.w = (v.w-mean)*inv*gg.w + bb.w;
    ((float4*)(out + (size_t)row*DD))[tid] = o4;
}

// split helper: v = hi + lo with hi = tf32(v)
__device__ __forceinline__ void tf32_split(float v, float& hi, float& lo){
    hi = wmma::__float_to_tf32(v);
    lo = wmma::__float_to_tf32(v - hi);
}

// ---------------- 3xTF32 GEMM: C = epi(A[M,K]@W[K,N]) ----------------
// tile 128x64, BK=16, 8 warps (4x2), warp tile 32x32 (2x2 of 16x16)
__global__ __launch_bounds__(256) void k_gemm(
    const float* __restrict__ A, int lda,
    const float* __restrict__ W,
    const float* __restrict__ bias,
    const float* __restrict__ residual,
    const float* __restrict__ rowscale,   // durations (per-row scalar) or null
    const float* __restrict__ colvec,     // Wdur
    const float* __restrict__ colbias,    // bdur
    float* __restrict__ C,
    int N, int K, int gelu)
{
    __shared__ float smem_[9216];                       // 36 KB
    float (*Ah)[24] = (float(*)[24])(smem_);            // 128x16 hi
    float (*Al)[24] = (float(*)[24])(smem_ + 3072);     // 128x16 lo
    float (*Bh)[72] = (float(*)[72])(smem_ + 6144);     // 16x64 hi
    float (*Bl)[72] = (float(*)[72])(smem_ + 7296);     // 16x64 lo
    float (*Cs)[72] = (float(*)[72])(smem_);            // 128x72 epilogue alias

    int tid = threadIdx.x, wid = tid>>5;
    int wm = wid & 3, wn = wid >> 2;
    int tile_n = blockIdx.x*64, tile_m = blockIdx.y*128;

    wmma::fragment<wmma::accumulator,16,16,8,float> acc[2][2];
    #pragma unroll
    for (int i=0;i<2;i++)
        #pragma unroll
        for (int j=0;j<2;j++) wmma::fill_fragment(acc[i][j], 0.f);

    for (int k0=0; k0<K; k0+=16){
        #pragma unroll
        for (int t=0;t<2;t++){
            int i = tid + t*256;               // 512 float4 loads for A tile
            int r = i>>2, c4 = i&3;
            float4 v = *(const float4*)(A + (size_t)(tile_m+r)*lda + k0 + c4*4);
            float hi,lo;
            tf32_split(v.x,hi,lo); Ah[r][c4*4+0]=hi; Al[r][c4*4+0]=lo;
            tf32_split(v.y,hi,lo); Ah[r][c4*4+1]=hi; Al[r][c4*4+1]=lo;
            tf32_split(v.z,hi,lo); Ah[r][c4*4+2]=hi; Al[r][c4*4+2]=lo;
            tf32_split(v.w,hi,lo); Ah[r][c4*4+3]=hi; Al[r][c4*4+3]=lo;
        }
        {
            int r = tid>>4, c4 = tid&15;       // 256 float4 loads for B tile
            float4 v = *(const float4*)(W + (size_t)(k0+r)*N + tile_n + c4*4);
            float hi,lo;
            tf32_split(v.x,hi,lo); Bh[r][c4*4+0]=hi; Bl[r][c4*4+0]=lo;
            tf32_split(v.y,hi,lo); Bh[r][c4*4+1]=hi; Bl[r][c4*4+1]=lo;
            tf32_split(v.z,hi,lo); Bh[r][c4*4+2]=hi; Bl[r][c4*4+2]=lo;
            tf32_split(v.w,hi,lo); Bh[r][c4*4+3]=hi; Bl[r][c4*4+3]=lo;
        }
        __syncthreads();
        #pragma unroll
        for (int kk=0; kk<16; kk+=8){
            wmma::fragment<wmma::matrix_a,16,16,8,wmma::precision::tf32,wmma::row_major> ah[2], al[2];
            wmma::fragment<wmma::matrix_b,16,16,8,wmma::precision::tf32,wmma::row_major> bh[2], bl[2];
            wmma::load_matrix_sync(ah[0], &Ah[wm*32   ][kk], 24);
            wmma::load_matrix_sync(ah[1], &Ah[wm*32+16][kk], 24);
            wmma::load_matrix_sync(al[0], &Al[wm*32   ][kk], 24);
            wmma::load_matrix_sync(al[1], &Al[wm*32+16][kk], 24);
            wmma::load_matrix_sync(bh[0], &Bh[kk][wn*32   ], 72);
            wmma::load_matrix_sync(bh[1], &Bh[kk][wn*32+16], 72);
            wmma::load_matrix_sync(bl[0], &Bl[kk][wn*32   ], 72);
            wmma::load_matrix_sync(bl[1], &Bl[kk][wn*32+16], 72);
            #pragma unroll
            for (int i=0;i<2;i++)
                #pragma unroll
                for (int j=0;j<2;j++){
                    wmma::mma_sync(acc[i][j], ah[i], bl[j], acc[i][j]);
                    wmma::mma_sync(acc[i][j], al[i], bh[j], acc[i][j]);
                    wmma::mma_sync(acc[i][j], ah[i], bh[j], acc[i][j]);
                }
        }
        __syncthreads();
    }

    #pragma unroll
    for (int i=0;i<2;i++)
        #pragma unroll
        for (int j=0;j<2;j++)
            wmma::store_matrix_sync(&Cs[wm*32+i*16][wn*32+j*16], acc[i][j], 72, wmma::mem_row_major);
    __syncthreads();

    #pragma unroll
    for (int t=0;t<32;t++){
        int i = tid + t*256;                   // 128*64 elements
        int r = i>>6, c = i&63;
        float v = Cs[r][c];
        int gr = tile_m + r, gc = tile_n + c;
        if (bias)     v += bias[gc];
        if (rowscale) v += rowscale[gr]*colvec[gc] + colbias[gc];
        if (gelu)     v  = 0.5f*v*(1.f + erff(v*0.70710678118f));
        if (residual) v += residual[(size_t)gr*N + gc];
        C[(size_t)gr*N + gc] = v;
    }
}

// ---------------- scores = scale * Q·K^T, masked (3xTF32) ----------------
// grid (kt=8, qt=8, bh=64), block 128 (4 warps 2x2), tile 64x64, d chunks of 32
__global__ __launch_bounds__(128) void k_scores(const float* __restrict__ qb,
                                                const float* __restrict__ kb,
                                                const int* __restrict__ mask,
                                                float* __restrict__ sc){
    __shared__ float smem_[9216];
    float (*Qh)[36] = (float(*)[36])(smem_);
    float (*Ql)[36] = (float(*)[36])(smem_ + 2304);
    float (*Kh)[36] = (float(*)[36])(smem_ + 4608);
    float (*Kl)[36] = (float(*)[36])(smem_ + 6912);
    float (*Cs)[72] = (float(*)[72])(smem_);

    int tid = threadIdx.x;
    int kt = blockIdx.x, qt = blockIdx.y, bh = blockIdx.z;
    int b = bh >> 4, h = bh & 15;
    int wid = tid>>5, wm = wid&1, wn = wid>>1;

    wmma::fragment<wmma::accumulator,16,16,8,float> acc[2][2];
    #pragma unroll
    for (int i=0;i<2;i++)
        #pragma unroll
        for (int j=0;j<2;j++) wmma::fill_fragment(acc[i][j], 0.f);

    for (int dc=0; dc<64; dc+=32){
        #pragma unroll
        for (int t=0;t<4;t++){
            int i = tid + t*128;               // 512 rows*cols4 per operand
            int r = i>>3, c4 = i&7;
            float4 v  = *(const float4*)(qb + ((size_t)(qt*64+r)*BB + b)*DD + h*HDIM + dc + c4*4);
            float hi,lo;
            tf32_split(v.x,hi,lo); Qh[r][c4*4+0]=hi; Ql[r][c4*4+0]=lo;
            tf32_split(v.y,hi,lo); Qh[r][c4*4+1]=hi; Ql[r][c4*4+1]=lo;
            tf32_split(v.z,hi,lo); Qh[r][c4*4+2]=hi; Ql[r][c4*4+2]=lo;
            tf32_split(v.w,hi,lo); Qh[r][c4*4+3]=hi; Ql[r][c4*4+3]=lo;
            float4 v2 = *(const float4*)(kb + ((size_t)(kt*64+r)*BB + b)*DD + h*HDIM + dc + c4*4);
            tf32_split(v2.x,hi,lo); Kh[r][c4*4+0]=hi; Kl[r][c4*4+0]=lo;
            tf32_split(v2.y,hi,lo); Kh[r][c4*4+1]=hi; Kl[r][c4*4+1]=lo;
            tf32_split(v2.z,hi,lo); Kh[r][c4*4+2]=hi; Kl[r][c4*4+2]=lo;
            tf32_split(v2.w,hi,lo); Kh[r][c4*4+3]=hi; Kl[r][c4*4+3]=lo;
        }
        __syncthreads();
        #pragma unroll
        for (int kk=0; kk<32; kk+=8){
            wmma::fragment<wmma::matrix_a,16,16,8,wmma::precision::tf32,wmma::row_major> ah[2], al[2];
            wmma::fragment<wmma::matrix_b,16,16,8,wmma::precision::tf32,wmma::col_major> bh[2], bl[2];
            wmma::load_matrix_sync(ah[0], &Qh[wm*32   ][kk], 36);
            wmma::load_matrix_sync(ah[1], &Qh[wm*32+16][kk], 36);
            wmma::load_matrix_sync(al[0], &Ql[wm*32   ][kk], 36);
            wmma::load_matrix_sync(al[1], &Ql[wm*32+16][kk], 36);
            wmma::load_matrix_sync(bh[0], &Kh[wn*32   ][kk], 36);
            wmma::load_matrix_sync(bh[1], &Kh[wn*32+16][kk], 36);
            wmma::load_matrix_sync(bl[0], &Kl[wn*32   ][kk], 36);
            wmma::load_matrix_sync(bl[1], &Kl[wn*32+16][kk], 36);
            #pragma unroll
            for (int i=0;i<2;i++)
                #pragma unroll
                for (int j=0;j<2;j++){
                    wmma::mma_sync(acc[i][j], ah[i], bl[j], acc[i][j]);
                    wmma::mma_sync(acc[i][j], al[i], bh[j], acc[i][j]);
                    wmma::mma_sync(acc[i][j], ah[i], bh[j], acc[i][j]);
                }
        }
        __syncthreads();
    }
    #pragma unroll
    for (int i=0;i<2;i++)
        #pragma unroll
        for (int j=0;j<2;j++)
            wmma::store_matrix_sync(&Cs[wm*32+i*16][wn*32+j*16], acc[i][j], 72, wmma::mem_row_major);
    __syncthreads();

    float* out = sc + (size_t)bh*SQ*SQ;
    #pragma unroll
    for (int t=0;t<32;t++){
        int i = tid + t*128;
        int r = i>>6, c = i&63;
        int gk = kt*64 + c;
        float v = Cs[r][c]*0.125f;
        if (mask[b*SQ + gk]) v = -1e30f;
        out[(size_t)(qt*64+r)*SQ + gk] = v;
    }
}

// ---------------- row softmax over 512 ----------------
__global__ __launch_bounds__(128) void k_softmax(float* __restrict__ scores){
    size_t row = blockIdx.x;
    float4* p = (float4*)(scores + row*SQ);
    int tid = threadIdx.x;
    float4 v = p[tid];
    float m = fmaxf(fmaxf(v.x,v.y), fmaxf(v.z,v.w));
    #pragma unroll
    for (int o=16;o;o>>=1) m = fmaxf(m, __shfl_xor_sync(0xffffffffu,m,o));
    __shared__ float s1[4], s2[4];
    if ((tid&31)==0) s1[tid>>5] = m;
    __syncthreads();
    m = fmaxf(fmaxf(s1[0],s1[1]), fmaxf(s1[2],s1[3]));
    v.x = expf(v.x-m); v.y = expf(v.y-m); v.z = expf(v.z-m); v.w = expf(v.w-m);
    float s = v.x+v.y+v.z+v.w;
    #pragma unroll
    for (int o=16;o;o>>=1) s += __shfl_xor_sync(0xffffffffu,s,o);
    if ((tid&31)==0) s2[tid>>5] = s;
    __syncthreads();
    s = s2[0]+s2[1]+s2[2]+s2[3];
    float inv = 1.f/s;
    v.x*=inv; v.y*=inv; v.z*=inv; v.w*=inv;
    p[tid] = v;
}

// ---------------- attn = probs @ V (3xTF32) ----------------
// grid (qt=8, bh=64), block 128, tile 64x64, K=512 in 16 chunks of 32
__global__ __launch_bounds__(128) void k_attnv(const float* __restrict__ pr,
                                               const float* __restrict__ vb,
                                               float* __restrict__ at){
    __shared__ float smem_[9216];
    float (*Ph)[36] = (float(*)[36])(smem_);
    float (*Pl)[36] = (float(*)[36])(smem_ + 2304);
    float (*Vh)[72] = (float(*)[72])(smem_ + 4608);
    float (*Vl)[72] = (float(*)[72])(smem_ + 6912);
    float (*Cs)[72] = (float(*)[72])(smem_);

    int tid = threadIdx.x;
    int qt = blockIdx.x, bh = blockIdx.y;
    int b = bh >> 4, h = bh & 15;
    int wid = tid>>5, wm = wid&1, wn = wid>>1;

    wmma::fragment<wmma::accumulator,16,16,8,float> acc[2][2];
    #pragma unroll
    for (int i=0;i<2;i++)
        #pragma unroll
        for (int j=0;j<2;j++) wmma::fill_fragment(acc[i][j], 0.f);

    const float* prb = pr + (size_t)bh*SQ*SQ;
    for (int kc=0; kc<16; kc++){
        #pragma unroll
        for (int t=0;t<4;t++){
            int i = tid + t*128;
            // P chunk: 64 rows x 32 cols
            int r = i>>3, c4 = i&7;
            float4 v = *(const float4*)(prb + (size_t)(qt*64+r)*SQ + kc*32 + c4*4);
            float hi,lo;
            tf32_split(v.x,hi,lo); Ph[r][c4*4+0]=hi; Pl[r][c4*4+0]=lo;
            tf32_split(v.y,hi,lo); Ph[r][c4*4+1]=hi; Pl[r][c4*4+1]=lo;
            tf32_split(v.z,hi,lo); Ph[r][c4*4+2]=hi; Pl[r][c4*4+2]=lo;
            tf32_split(v.w,hi,lo); Ph[r][c4*4+3]=hi; Pl[r][c4*4+3]=lo;
            // V chunk: 32 rows x 64 cols
            int r2 = i>>4, c42 = i&15;
            float4 v2 = *(const float4*)(vb + ((size_t)(kc*32+r2)*BB + b)*DD + h*HDIM + c42*4);
            tf32_split(v2.x,hi,lo); Vh[r2][c42*4+0]=hi; Vl[r2][c42*4+0]=lo;
            tf32_split(v2.y,hi,lo); Vh[r2][c42*4+1]=hi; Vl[r2][c42*4+1]=lo;
            tf32_split(v2.z,hi,lo); Vh[r2][c42*4+2]=hi; Vl[r2][c42*4+2]=lo;
            tf32_split(v2.w,hi,lo); Vh[r2][c42*4+3]=hi; Vl[r2][c42*4+3]=lo;
        }
        __syncthreads();
        #pragma unroll
        for (int kk=0; kk<32; kk+=8){
            wmma::fragment<wmma::matrix_a,16,16,8,wmma::precision::tf32,wmma::row_major> ah[2], al[2];
            wmma::fragment<wmma::matrix_b,16,16,8,wmma::precision::tf32,wmma::row_major> bh[2], bl[2];
            wmma::load_matrix_sync(ah[0], &Ph[wm*32   ][kk], 36);
            wmma::load_matrix_sync(ah[1], &Ph[wm*32+16][kk], 36);
            wmma::load_matrix_sync(al[0], &Pl[wm*32   ][kk], 36);
            wmma::load_matrix_sync(al[1], &Pl[wm*32+16][kk], 36);
            wmma::load_matrix_sync(bh[0], &Vh[kk][wn*32   ], 72);
            wmma::load_matrix_sync(bh[1], &Vh[kk][wn*32+16], 72);
            wmma::load_matrix_sync(bl[0], &Vl[kk][wn*32   ], 72);
            wmma::load_matrix_sync(bl[1], &Vl[kk][wn*32+16], 72);
            #pragma unroll
            for (int i=0;i<2;i++)
                #pragma unroll
                for (int j=0;j<2;j++){
                    wmma::mma_sync(acc[i][j], ah[i], bl[j], acc[i][j]);
                    wmma::mma_sync(acc[i][j], al[i], bh[j], acc[i][j]);
                    wmma::mma_sync(acc[i][j], ah[i], bh[j], acc[i][j]);
                }
        }
        __syncthreads();
    }
    #pragma unroll
    for (int i=0;i<2;i++)
        #pragma unroll
        for (int j=0;j<2;j++)
            wmma::store_matrix_sync(&Cs[wm*32+i*16][wn*32+j*16], acc[i][j], 72, wmma::mem_row_major);
    __syncthreads();
    #pragma unroll
    for (int t=0;t<32;t++){
        int i = tid + t*128;
        int r = i>>6, c = i&63;
        at[((size_t)(qt*64+r)*BB + b)*DD + h*HDIM + c] = Cs[r][c];
    }
}

// ---------------- host ----------------
extern "C" void kernel_launch(void* const* d_in, const int* in_sizes, int n_in,
                              void* d_out, int out_size){
    const float* segments  = (const float*)d_in[0];
    const float* durations = (const float*)d_in[1];
    const unsigned char* maskraw = (const unsigned char*)d_in[2];
    const float* Wproj = (const float*)d_in[3];
    const float* bproj = (const float*)d_in[4];
    const float* Wdur  = (const float*)d_in[5];
    const float* bdur  = (const float*)d_in[6];
    const float* ln1g  = (const float*)d_in[7];
    const float* ln1b  = (const float*)d_in[8];
    const float* Wq    = (const float*)d_in[9];
    const float* bq    = (const float*)d_in[10];
    const float* Wk    = (const float*)d_in[11];
    const float* bk    = (const float*)d_in[12];
    const float* Wv    = (const float*)d_in[13];
    const float* bv    = (const float*)d_in[14];
    const float* Wo    = (const float*)d_in[15];
    const float* bo    = (const float*)d_in[16];
    const float* ln2g  = (const float*)d_in[17];
    const float* ln2b  = (const float*)d_in[18];
    const float* W1    = (const float*)d_in[19];
    const float* b1    = (const float*)d_in[20];
    const float* W2    = (const float*)d_in[21];
    const float* b2    = (const float*)d_in[22];

    float *px,*ph,*pq,*pk,*pv,*pat,*pfh,*psc,*prc;
    int* pmask;
    cudaGetSymbolAddress((void**)&px,  g_x);
    cudaGetSymbolAddress((void**)&ph,  g_h);
    cudaGetSymbolAddress((void**)&pq,  g_q);
    cudaGetSymbolAddress((void**)&pk,  g_k);
    cudaGetSymbolAddress((void**)&pv,  g_v);
    cudaGetSymbolAddress((void**)&pat, g_attn);
    cudaGetSymbolAddress((void**)&pfh, g_ffh);
    cudaGetSymbolAddress((void**)&psc, g_scores);
    cudaGetSymbolAddress((void**)&prc, g_rope);
    cudaGetSymbolAddress((void**)&pmask, g_mask);

    k_mask_prep<<<1,256>>>(maskraw, pmask);
    k_rope_cache<<<64,256>>>(prc);

    // x = segments@Wproj + bproj + dur*Wdur + bdur
    k_gemm<<<dim3(16,16),256>>>(segments, DIN_, Wproj, bproj, nullptr,
                                durations, Wdur, bdur, px, DD, DIN_, 0);

    for (int l=0; l<LAYERS; l++){
        size_t wdd = (size_t)l*DD*DD;
        k_ln<<<MROWS,256>>>(px, ln1g + l*DD, ln1b + l*DD, ph);

        k_gemm<<<dim3(16,16),256>>>(ph, DD, Wq + wdd, bq + l*DD, nullptr,
                                    nullptr,nullptr,nullptr, pq, DD, DD, 0);
        k_gemm<<<dim3(16,16),256>>>(ph, DD, Wk + wdd, bk + l*DD, nullptr,
                                    nullptr,nullptr,nullptr, pk, DD, DD, 0);
        k_gemm<<<dim3(16,16),256>>>(ph, DD, Wv + wdd, bv + l*DD, nullptr,
                                    nullptr,nullptr,nullptr, pv, DD, DD, 0);

        k_rope_apply<<<4096,256>>>(pq, pk, prc);

        k_scores<<<dim3(8,8,BB*HH),128>>>(pq, pk, pmask, psc);
        k_softmax<<<BB*HH*SQ,128>>>(psc);
        k_attnv<<<dim3(8,BB*HH),128>>>(psc, pv, pat);

        // x = x + attn@Wo + bo
        k_gemm<<<dim3(16,16),256>>>(pat, DD, Wo + wdd, bo + l*DD, px,
                                    nullptr,nullptr,nullptr, px, DD, DD, 0);

        k_ln<<<MROWS,256>>>(px, ln2g + l*DD, ln2b + l*DD, ph);

        // ffh = gelu(h@W1 + b1)
        k_gemm<<<dim3(64,16),256>>>(ph, DD, W1 + (size_t)l*DD*FF_, b1 + l*FF_, nullptr,
                                    nullptr,nullptr,nullptr, pfh, FF_, DD, 1);

        // x = x + ffh@W2 + b2   (last layer writes straight into d_out)
        float* outp = (l == LAYERS-1) ? (float*)d_out : px;
        k_gemm<<<dim3(16,16),256>>>(pfh, FF_, W2 + (size_t)l*FF_*DD, b2 + l*DD, px,
                                    nullptr,nullptr,nullptr, outp, DD, FF_, 0);
    }
}

// round 6
// speedup vs baseline: 1.0146x; 1.0146x over previous
#include <cuda_runtime.h>
#include <mma.h>
#include <cstdint>

using namespace nvcuda;

#define SQ   512
#define BB   4
#define DIN_ 768
#define DD   1024
#define HH   16
#define HDIM 64
#define FF_  4096
#define MROWS 2048   // S*B
#define LAYERS 12

// ---------------- device scratch (no allocs allowed) ----------------
__device__ float g_x   [MROWS*DD];
__device__ float g_h   [MROWS*DD];
__device__ float g_q   [MROWS*DD];
__device__ float g_k   [MROWS*DD];
__device__ float g_v   [MROWS*DD];
__device__ float g_attn[MROWS*DD];
__device__ float g_ffh [MROWS*FF_];
__device__ float g_scores[(size_t)BB*HH*SQ*SQ];
__device__ float g_rope[SQ*32*2];   // interleaved cos,sin per (s, j<32)
__device__ int   g_mask[BB*SQ];     // canonical 0/1 key mask

// ---------------- mask canonicalization (bool / int32 / float32 robust) ----
__global__ void k_mask_prep(const unsigned char* __restrict__ raw,
                            int* __restrict__ outm){
    __shared__ int s_float, s_bool;
    if (threadIdx.x==0){ s_float=0; s_bool=0; }
    __syncthreads();
    for (int i=threadIdx.x; i<BB*SQ; i+=256){
        unsigned char v = raw[i];
        if ((i&3)==3 && v==0x3f) atomicOr(&s_float,1);   // 1.0f byte pattern
        else if ((i&3)!=0 && v!=0) atomicOr(&s_bool,1);  // random bools
    }
    __syncthreads();
    int mode = s_float ? 2 : (s_bool ? 0 : 1); // 0=bool, 1=int32, 2=float32
    for (int i=threadIdx.x; i<BB*SQ; i+=256){
        int m;
        if (mode==0)      m = raw[i] != 0;
        else if (mode==1) m = ((const int*)raw)[i] != 0;
        else              m = ((const float*)raw)[i] != 0.f;
        outm[i] = m;
    }
}

// ---------------- RoPE cache ----------------
__global__ void k_rope_cache(float* __restrict__ cache){
    int i = blockIdx.x*blockDim.x + threadIdx.x;
    if (i >= SQ*32) return;
    int s = i >> 5, j = i & 31;
    float invf = powf(10000.f, -((float)(2*j)) / 64.f);
    float a = (float)s * invf;
    cache[2*i]   = cosf(a);
    cache[2*i+1] = sinf(a);
}

__global__ __launch_bounds__(256) void k_rope_apply(float* __restrict__ q,
                                                    float* __restrict__ k,
                                                    const float* __restrict__ cache){
    int i = blockIdx.x*256 + threadIdx.x;        // < 2048*16*32
    int j = i & 31;
    int h = (i >> 5) & 15;
    int r = i >> 9;                               // row = s*B+b
    int s = r >> 2;                               // B=4
    float c  = cache[(s*32+j)*2];
    float sn = cache[(s*32+j)*2+1];
    size_t base = (size_t)r*DD + h*HDIM;
    float a1 = q[base+j], a2 = q[base+j+32];
    q[base+j]    = a1*c - a2*sn;
    q[base+j+32] = a2*c + a1*sn;
    float b1 = k[base+j], b2 = k[base+j+32];
    k[base+j]    = b1*c - b2*sn;
    k[base+j+32] = b2*c + b1*sn;
}

// ---------------- LayerNorm ----------------
__global__ __launch_bounds__(256) void k_ln(const float* __restrict__ x,
                                            const float* __restrict__ g,
                                            const float* __restrict__ b,
                                            float* __restrict__ out){
    int row = blockIdx.x, tid = threadIdx.x;
    const float4* xr = (const float4*)(x + (size_t)row*DD);
    float4 v = xr[tid];
    float s  = v.x+v.y+v.z+v.w;
    float q2 = v.x*v.x+v.y*v.y+v.z*v.z+v.w*v.w;
    #pragma unroll
    for (int o=16;o;o>>=1){ s += __shfl_xor_sync(0xffffffffu,s,o);
                            q2 += __shfl_xor_sync(0xffffffffu,q2,o); }
    __shared__ float ss[8], sq[8];
    if ((tid&31)==0){ ss[tid>>5]=s; sq[tid>>5]=q2; }
    __syncthreads();
    float S_=0.f, Q_=0.f;
    #pragma unroll
    for (int i=0;i<8;i++){ S_+=ss[i]; Q_+=sq[i]; }
    float mean = S_ * (1.f/DD);
    float var  = Q_ * (1.f/DD) - mean*mean;
    float inv  = rsqrtf(var + 1e-5f);
    float4 gg = ((const float4*)g)[tid];
    float4 bb = ((const float4*)b)[tid];
    float4 o4;
    o4.x = (v.x-mean)*inv*gg.x + bb.x;
    o4.y = (v.y-mean)*inv*gg.y + bb.y;
    o4.z = (v.z-mean)*inv*gg.z + bb.z;
    o4.w = (v.w-mean)*inv*gg.w + bb.w;
    ((float4*)(out + (size_t)row*DD))[tid] = o4;
}

// split helper: v = hi + lo with hi = tf32(v)
__device__ __forceinline__ void tf32_split(float v, float& hi, float& lo){
    hi = wmma::__float_to_tf32(v);
    lo = wmma::__float_to_tf32(v - hi);
}

// ======================================================================
// 3xTF32 GEMM, double-buffered. C = epi(A[M,K] @ W[K,N])
// CTA tile 128x64, BK=16, 8 warps (4x2), warp tile 32x32.
// Dynamic smem: 2 stages x (Ah 128x20 | Al 128x20 | Bh 16x68 | Bl 16x68)
//   stage = 7296 floats; total 14592 floats = 58368 B.
// Epilogue reuses smem as 8 per-warp 32x36 staging tiles (9216 floats).
// ======================================================================
#define G_STAGE 7296
#define G_SMEM_BYTES 58368

__global__ __launch_bounds__(256) void k_gemm(
    const float* __restrict__ A, int lda,
    const float* __restrict__ W,
    const float* __restrict__ bias,
    const float* __restrict__ residual,
    const float* __restrict__ rowscale,   // durations (per-row scalar) or null
    const float* __restrict__ colvec,     // Wdur
    const float* __restrict__ colbias,    // bdur
    float* __restrict__ C,
    int N, int K, int gelu)
{
    extern __shared__ float sm[];

    int tid = threadIdx.x, wid = tid>>5, lid = tid&31;
    int wm = wid & 3, wn = wid >> 2;
    int tile_n = blockIdx.x*64, tile_m = blockIdx.y*128;

    // load indices
    int ar0 = tid>>2,        ac = (tid&3)*4;      // A: 2 float4/thread
    int ar1 = ar0 + 64;
    int br  = tid>>4;        int bc = (tid&15)*4; // B: 1 float4/thread

    const float* Arow0 = A + (size_t)(tile_m+ar0)*lda + ac;
    const float* Arow1 = A + (size_t)(tile_m+ar1)*lda + ac;
    const float* Brow  = W + (size_t)br*N + tile_n + bc;

    wmma::fragment<wmma::accumulator,16,16,8,float> acc[2][2];
    #pragma unroll
    for (int i=0;i<2;i++)
        #pragma unroll
        for (int j=0;j<2;j++) wmma::fill_fragment(acc[i][j], 0.f);

    int nch = K >> 4;
    float4 ra0, ra1, rb;

    // prologue: chunk 0
    ra0 = *(const float4*)(Arow0);
    ra1 = *(const float4*)(Arow1);
    rb  = *(const float4*)(Brow);
    {
        float* AH = sm;            float* AL = sm + 2560;
        float* BH = sm + 5120;     float* BL = sm + 6208;
        float hi,lo;
        tf32_split(ra0.x,hi,lo); AH[ar0*20+ac+0]=hi; AL[ar0*20+ac+0]=lo;
        tf32_split(ra0.y,hi,lo); AH[ar0*20+ac+1]=hi; AL[ar0*20+ac+1]=lo;
        tf32_split(ra0.z,hi,lo); AH[ar0*20+ac+2]=hi; AL[ar0*20+ac+2]=lo;
        tf32_split(ra0.w,hi,lo); AH[ar0*20+ac+3]=hi; AL[ar0*20+ac+3]=lo;
        tf32_split(ra1.x,hi,lo); AH[ar1*20+ac+0]=hi; AL[ar1*20+ac+0]=lo;
        tf32_split(ra1.y,hi,lo); AH[ar1*20+ac+1]=hi; AL[ar1*20+ac+1]=lo;
        tf32_split(ra1.z,hi,lo); AH[ar1*20+ac+2]=hi; AL[ar1*20+ac+2]=lo;
        tf32_split(ra1.w,hi,lo); AH[ar1*20+ac+3]=hi; AL[ar1*20+ac+3]=lo;
        tf32_split(rb.x,hi,lo);  BH[br*68+bc+0]=hi;  BL[br*68+bc+0]=lo;
        tf32_split(rb.y,hi,lo);  BH[br*68+bc+1]=hi;  BL[br*68+bc+1]=lo;
        tf32_split(rb.z,hi,lo);  BH[br*68+bc+2]=hi;  BL[br*68+bc+2]=lo;
        tf32_split(rb.w,hi,lo);  BH[br*68+bc+3]=hi;  BL[br*68+bc+3]=lo;
    }
    __syncthreads();

    for (int ch=0; ch<nch; ch++){
        int cur = ch & 1;
        // prefetch next chunk into registers (overlaps with MMA below)
        if (ch+1 < nch){
            int k0 = (ch+1)<<4;
            ra0 = *(const float4*)(Arow0 + k0);
            ra1 = *(const float4*)(Arow1 + k0);
            rb  = *(const float4*)(Brow  + (size_t)k0*N);
        }
        // MMA on current stage
        {
            float* AH = sm + cur*G_STAGE;
            float* AL = AH + 2560;
            float* BH = AH + 5120;
            float* BL = AH + 6208;
            #pragma unroll
            for (int kk=0; kk<16; kk+=8){
                wmma::fragment<wmma::matrix_a,16,16,8,wmma::precision::tf32,wmma::row_major> ah[2], al[2];
                wmma::fragment<wmma::matrix_b,16,16,8,wmma::precision::tf32,wmma::row_major> bh[2], bl[2];
                wmma::load_matrix_sync(ah[0], AH + (wm*32   )*20 + kk, 20);
                wmma::load_matrix_sync(ah[1], AH + (wm*32+16)*20 + kk, 20);
                wmma::load_matrix_sync(al[0], AL + (wm*32   )*20 + kk, 20);
                wmma::load_matrix_sync(al[1], AL + (wm*32+16)*20 + kk, 20);
                wmma::load_matrix_sync(bh[0], BH + kk*68 + wn*32,      68);
                wmma::load_matrix_sync(bh[1], BH + kk*68 + wn*32+16,   68);
                wmma::load_matrix_sync(bl[0], BL + kk*68 + wn*32,      68);
                wmma::load_matrix_sync(bl[1], BL + kk*68 + wn*32+16,   68);
                #pragma unroll
                for (int i=0;i<2;i++)
                    #pragma unroll
                    for (int j=0;j<2;j++){
                        wmma::mma_sync(acc[i][j], ah[i], bl[j], acc[i][j]);
                        wmma::mma_sync(acc[i][j], al[i], bh[j], acc[i][j]);
                        wmma::mma_sync(acc[i][j], ah[i], bh[j], acc[i][j]);
                    }
            }
        }
        // split + store next stage
        if (ch+1 < nch){
            float* AH = sm + (cur^1)*G_STAGE;
            float* AL = AH + 2560;
            float* BH = AH + 5120;
            float* BL = AH + 6208;
            float hi,lo;
            tf32_split(ra0.x,hi,lo); AH[ar0*20+ac+0]=hi; AL[ar0*20+ac+0]=lo;
            tf32_split(ra0.y,hi,lo); AH[ar0*20+ac+1]=hi; AL[ar0*20+ac+1]=lo;
            tf32_split(ra0.z,hi,lo); AH[ar0*20+ac+2]=hi; AL[ar0*20+ac+2]=lo;
            tf32_split(ra0.w,hi,lo); AH[ar0*20+ac+3]=hi; AL[ar0*20+ac+3]=lo;
            tf32_split(ra1.x,hi,lo); AH[ar1*20+ac+0]=hi; AL[ar1*20+ac+0]=lo;
            tf32_split(ra1.y,hi,lo); AH[ar1*20+ac+1]=hi; AL[ar1*20+ac+1]=lo;
            tf32_split(ra1.z,hi,lo); AH[ar1*20+ac+2]=hi; AL[ar1*20+ac+2]=lo;
            tf32_split(ra1.w,hi,lo); AH[ar1*20+ac+3]=hi; AL[ar1*20+ac+3]=lo;
            tf32_split(rb.x,hi,lo);  BH[br*68+bc+0]=hi;  BL[br*68+bc+0]=lo;
            tf32_split(rb.y,hi,lo);  BH[br*68+bc+1]=hi;  BL[br*68+bc+1]=lo;
            tf32_split(rb.z,hi,lo);  BH[br*68+bc+2]=hi;  BL[br*68+bc+2]=lo;
            tf32_split(rb.w,hi,lo);  BH[br*68+bc+3]=hi;  BL[br*68+bc+3]=lo;
        }
        __syncthreads();
    }

    // ---------------- epilogue: per-warp smem staging ----------------
    float* stg = sm + wid*1152;               // 32x36
    #pragma unroll
    for (int i=0;i<2;i++)
        #pragma unroll
        for (int j=0;j<2;j++)
            wmma::store_matrix_sync(stg + i*16*36 + j*16, acc[i][j], 36, wmma::mem_row_major);
    __syncwarp();

    #pragma unroll
    for (int t=0;t<8;t++){
        int idx = lid + t*32;                 // 256 float4 per warp (32x32)
        int r = idx>>3, c4 = idx&7;
        int gr = tile_m + wm*32 + r;
        int gc = tile_n + wn*32 + c4*4;
        float4 v = *(const float4*)(stg + r*36 + c4*4);
        if (bias){
            float4 bb = *(const float4*)(bias + gc);
            v.x+=bb.x; v.y+=bb.y; v.z+=bb.z; v.w+=bb.w;
        }
        if (rowscale){
            float rs = rowscale[gr];
            float4 cv = *(const float4*)(colvec + gc);
            float4 cb = *(const float4*)(colbias + gc);
            v.x += rs*cv.x + cb.x; v.y += rs*cv.y + cb.y;
            v.z += rs*cv.z + cb.z; v.w += rs*cv.w + cb.w;
        }
        if (gelu){
            v.x = 0.5f*v.x*(1.f + erff(v.x*0.70710678118f));
            v.y = 0.5f*v.y*(1.f + erff(v.y*0.70710678118f));
            v.z = 0.5f*v.z*(1.f + erff(v.z*0.70710678118f));
            v.w = 0.5f*v.w*(1.f + erff(v.w*0.70710678118f));
        }
        if (residual){
            float4 rr = *(const float4*)(residual + (size_t)gr*N + gc);
            v.x+=rr.x; v.y+=rr.y; v.z+=rr.z; v.w+=rr.w;
        }
        *(float4*)(C + (size_t)gr*N + gc) = v;
    }
}

// ---------------- scores = scale * Q·K^T, masked (3xTF32) ----------------
__global__ __launch_bounds__(128) void k_scores(const float* __restrict__ qb,
                                                const float* __restrict__ kb,
                                                const int* __restrict__ mask,
                                                float* __restrict__ sc){
    __shared__ float smem_[9216];
    float (*Qh)[36] = (float(*)[36])(smem_);
    float (*Ql)[36] = (float(*)[36])(smem_ + 2304);
    float (*Kh)[36] = (float(*)[36])(smem_ + 4608);
    float (*Kl)[36] = (float(*)[36])(smem_ + 6912);
    float (*Cs)[72] = (float(*)[72])(smem_);

    int tid = threadIdx.x;
    int kt = blockIdx.x, qt = blockIdx.y, bh = blockIdx.z;
    int b = bh >> 4, h = bh & 15;
    int wid = tid>>5, wm = wid&1, wn = wid>>1;

    wmma::fragment<wmma::accumulator,16,16,8,float> acc[2][2];
    #pragma unroll
    for (int i=0;i<2;i++)
        #pragma unroll
        for (int j=0;j<2;j++) wmma::fill_fragment(acc[i][j], 0.f);

    for (int dc=0; dc<64; dc+=32){
        #pragma unroll
        for (int t=0;t<4;t++){
            int i = tid + t*128;
            int r = i>>3, c4 = i&7;
            float4 v  = *(const float4*)(qb + ((size_t)(qt*64+r)*BB + b)*DD + h*HDIM + dc + c4*4);
            float hi,lo;
            tf32_split(v.x,hi,lo); Qh[r][c4*4+0]=hi; Ql[r][c4*4+0]=lo;
            tf32_split(v.y,hi,lo); Qh[r][c4*4+1]=hi; Ql[r][c4*4+1]=lo;
            tf32_split(v.z,hi,lo); Qh[r][c4*4+2]=hi; Ql[r][c4*4+2]=lo;
            tf32_split(v.w,hi,lo); Qh[r][c4*4+3]=hi; Ql[r][c4*4+3]=lo;
            float4 v2 = *(const float4*)(kb + ((size_t)(kt*64+r)*BB + b)*DD + h*HDIM + dc + c4*4);
            tf32_split(v2.x,hi,lo); Kh[r][c4*4+0]=hi; Kl[r][c4*4+0]=lo;
            tf32_split(v2.y,hi,lo); Kh[r][c4*4+1]=hi; Kl[r][c4*4+1]=lo;
            tf32_split(v2.z,hi,lo); Kh[r][c4*4+2]=hi; Kl[r][c4*4+2]=lo;
            tf32_split(v2.w,hi,lo); Kh[r][c4*4+3]=hi; Kl[r][c4*4+3]=lo;
        }
        __syncthreads();
        #pragma unroll
        for (int kk=0; kk<32; kk+=8){
            wmma::fragment<wmma::matrix_a,16,16,8,wmma::precision::tf32,wmma::row_major> ah[2], al[2];
            wmma::fragment<wmma::matrix_b,16,16,8,wmma::precision::tf32,wmma::col_major> bh[2], bl[2];
            wmma::load_matrix_sync(ah[0], &Qh[wm*32   ][kk], 36);
            wmma::load_matrix_sync(ah[1], &Qh[wm*32+16][kk], 36);
            wmma::load_matrix_sync(al[0], &Ql[wm*32   ][kk], 36);
            wmma::load_matrix_sync(al[1], &Ql[wm*32+16][kk], 36);
            wmma::load_matrix_sync(bh[0], &Kh[wn*32   ][kk], 36);
            wmma::load_matrix_sync(bh[1], &Kh[wn*32+16][kk], 36);
            wmma::load_matrix_sync(bl[0], &Kl[wn*32   ][kk], 36);
            wmma::load_matrix_sync(bl[1], &Kl[wn*32+16][kk], 36);
            #pragma unroll
            for (int i=0;i<2;i++)
                #pragma unroll
                for (int j=0;j<2;j++){
                    wmma::mma_sync(acc[i][j], ah[i], bl[j], acc[i][j]);
                    wmma::mma_sync(acc[i][j], al[i], bh[j], acc[i][j]);
                    wmma::mma_sync(acc[i][j], ah[i], bh[j], acc[i][j]);
                }
        }
        __syncthreads();
    }
    #pragma unroll
    for (int i=0;i<2;i++)
        #pragma unroll
        for (int j=0;j<2;j++)
            wmma::store_matrix_sync(&Cs[wm*32+i*16][wn*32+j*16], acc[i][j], 72, wmma::mem_row_major);
    __syncthreads();

    float* out = sc + (size_t)bh*SQ*SQ;
    #pragma unroll
    for (int t=0;t<32;t++){
        int i = tid + t*128;
        int r = i>>6, c = i&63;
        int gk = kt*64 + c;
        float v = Cs[r][c]*0.125f;
        if (mask[b*SQ + gk]) v = -1e30f;
        out[(size_t)(qt*64+r)*SQ + gk] = v;
    }
}

// ---------------- row softmax over 512 ----------------
__global__ __launch_bounds__(128) void k_softmax(float* __restrict__ scores){
    size_t row = blockIdx.x;
    float4* p = (float4*)(scores + row*SQ);
    int tid = threadIdx.x;
    float4 v = p[tid];
    float m = fmaxf(fmaxf(v.x,v.y), fmaxf(v.z,v.w));
    #pragma unroll
    for (int o=16;o;o>>=1) m = fmaxf(m, __shfl_xor_sync(0xffffffffu,m,o));
    __shared__ float s1[4], s2[4];
    if ((tid&31)==0) s1[tid>>5] = m;
    __syncthreads();
    m = fmaxf(fmaxf(s1[0],s1[1]), fmaxf(s1[2],s1[3]));
    v.x = expf(v.x-m); v.y = expf(v.y-m); v.z = expf(v.z-m); v.w = expf(v.w-m);
    float s = v.x+v.y+v.z+v.w;
    #pragma unroll
    for (int o=16;o;o>>=1) s += __shfl_xor_sync(0xffffffffu,s,o);
    if ((tid&31)==0) s2[tid>>5] = s;
    __syncthreads();
    s = s2[0]+s2[1]+s2[2]+s2[3];
    float inv = 1.f/s;
    v.x*=inv; v.y*=inv; v.z*=inv; v.w*=inv;
    p[tid] = v;
}

// ---------------- attn = probs @ V (3xTF32) ----------------
__global__ __launch_bounds__(128) void k_attnv(const float* __restrict__ pr,
                                               const float* __restrict__ vb,
                                               float* __restrict__ at){
    __shared__ float smem_[9216];
    float (*Ph)[36] = (float(*)[36])(smem_);
    float (*Pl)[36] = (float(*)[36])(smem_ + 2304);
    float (*Vh)[72] = (float(*)[72])(smem_ + 4608);
    float (*Vl)[72] = (float(*)[72])(smem_ + 6912);
    float (*Cs)[72] = (float(*)[72])(smem_);

    int tid = threadIdx.x;
    int qt = blockIdx.x, bh = blockIdx.y;
    int b = bh >> 4, h = bh & 15;
    int wid = tid>>5, wm = wid&1, wn = wid>>1;

    wmma::fragment<wmma::accumulator,16,16,8,float> acc[2][2];
    #pragma unroll
    for (int i=0;i<2;i++)
        #pragma unroll
        for (int j=0;j<2;j++) wmma::fill_fragment(acc[i][j], 0.f);

    const float* prb = pr + (size_t)bh*SQ*SQ;
    for (int kc=0; kc<16; kc++){
        #pragma unroll
        for (int t=0;t<4;t++){
            int i = tid + t*128;
            int r = i>>3, c4 = i&7;
            float4 v = *(const float4*)(prb + (size_t)(qt*64+r)*SQ + kc*32 + c4*4);
            float hi,lo;
            tf32_split(v.x,hi,lo); Ph[r][c4*4+0]=hi; Pl[r][c4*4+0]=lo;
            tf32_split(v.y,hi,lo); Ph[r][c4*4+1]=hi; Pl[r][c4*4+1]=lo;
            tf32_split(v.z,hi,lo); Ph[r][c4*4+2]=hi; Pl[r][c4*4+2]=lo;
            tf32_split(v.w,hi,lo); Ph[r][c4*4+3]=hi; Pl[r][c4*4+3]=lo;
            int r2 = i>>4, c42 = i&15;
            float4 v2 = *(const float4*)(vb + ((size_t)(kc*32+r2)*BB + b)*DD + h*HDIM + c42*4);
            tf32_split(v2.x,hi,lo); Vh[r2][c42*4+0]=hi; Vl[r2][c42*4+0]=lo;
            tf32_split(v2.y,hi,lo); Vh[r2][c42*4+1]=hi; Vl[r2][c42*4+1]=lo;
            tf32_split(v2.z,hi,lo); Vh[r2][c42*4+2]=hi; Vl[r2][c42*4+2]=lo;
            tf32_split(v2.w,hi,lo); Vh[r2][c42*4+3]=hi; Vl[r2][c42*4+3]=lo;
        }
        __syncthreads();
        #pragma unroll
        for (int kk=0; kk<32; kk+=8){
            wmma::fragment<wmma::matrix_a,16,16,8,wmma::precision::tf32,wmma::row_major> ah[2], al[2];
            wmma::fragment<wmma::matrix_b,16,16,8,wmma::precision::tf32,wmma::row_major> bh[2], bl[2];
            wmma::load_matrix_sync(ah[0], &Ph[wm*32   ][kk], 36);
            wmma::load_matrix_sync(ah[1], &Ph[wm*32+16][kk], 36);
            wmma::load_matrix_sync(al[0], &Pl[wm*32   ][kk], 36);
            wmma::load_matrix_sync(al[1], &Pl[wm*32+16][kk], 36);
            wmma::load_matrix_sync(bh[0], &Vh[kk][wn*32   ], 72);
            wmma::load_matrix_sync(bh[1], &Vh[kk][wn*32+16], 72);
            wmma::load_matrix_sync(bl[0], &Vl[kk][wn*32   ], 72);
            wmma::load_matrix_sync(bl[1], &Vl[kk][wn*32+16], 72);
            #pragma unroll
            for (int i=0;i<2;i++)
                #pragma unroll
                for (int j=0;j<2;j++){
                    wmma::mma_sync(acc[i][j], ah[i], bl[j], acc[i][j]);
                    wmma::mma_sync(acc[i][j], al[i], bh[j], acc[i][j]);
                    wmma::mma_sync(acc[i][j], ah[i], bh[j], acc[i][j]);
                }
        }
        __syncthreads();
    }
    #pragma unroll
    for (int i=0;i<2;i++)
        #pragma unroll
        for (int j=0;j<2;j++)
            wmma::store_matrix_sync(&Cs[wm*32+i*16][wn*32+j*16], acc[i][j], 72, wmma::mem_row_major);
    __syncthreads();
    #pragma unroll
    for (int t=0;t<32;t++){
        int i = tid + t*128;
        int r = i>>6, c = i&63;
        at[((size_t)(qt*64+r)*BB + b)*DD + h*HDIM + c] = Cs[r][c];
    }
}

// ---------------- host ----------------
extern "C" void kernel_launch(void* const* d_in, const int* in_sizes, int n_in,
                              void* d_out, int out_size){
    const float* segments  = (const float*)d_in[0];
    const float* durations = (const float*)d_in[1];
    const unsigned char* maskraw = (const unsigned char*)d_in[2];
    const float* Wproj = (const float*)d_in[3];
    const float* bproj = (const float*)d_in[4];
    const float* Wdur  = (const float*)d_in[5];
    const float* bdur  = (const float*)d_in[6];
    const float* ln1g  = (const float*)d_in[7];
    const float* ln1b  = (const float*)d_in[8];
    const float* Wq    = (const float*)d_in[9];
    const float* bq    = (const float*)d_in[10];
    const float* Wk    = (const float*)d_in[11];
    const float* bk    = (const float*)d_in[12];
    const float* Wv    = (const float*)d_in[13];
    const float* bv    = (const float*)d_in[14];
    const float* Wo    = (const float*)d_in[15];
    const float* bo    = (const float*)d_in[16];
    const float* ln2g  = (const float*)d_in[17];
    const float* ln2b  = (const float*)d_in[18];
    const float* W1    = (const float*)d_in[19];
    const float* b1    = (const float*)d_in[20];
    const float* W2    = (const float*)d_in[21];
    const float* b2    = (const float*)d_in[22];

    float *px,*ph,*pq,*pk,*pv,*pat,*pfh,*psc,*prc;
    int* pmask;
    cudaGetSymbolAddress((void**)&px,  g_x);
    cudaGetSymbolAddress((void**)&ph,  g_h);
    cudaGetSymbolAddress((void**)&pq,  g_q);
    cudaGetSymbolAddress((void**)&pk,  g_k);
    cudaGetSymbolAddress((void**)&pv,  g_v);
    cudaGetSymbolAddress((void**)&pat, g_attn);
    cudaGetSymbolAddress((void**)&pfh, g_ffh);
    cudaGetSymbolAddress((void**)&psc, g_scores);
    cudaGetSymbolAddress((void**)&prc, g_rope);
    cudaGetSymbolAddress((void**)&pmask, g_mask);

    cudaFuncSetAttribute(k_gemm, cudaFuncAttributeMaxDynamicSharedMemorySize, G_SMEM_BYTES);

    k_mask_prep<<<1,256>>>(maskraw, pmask);
    k_rope_cache<<<64,256>>>(prc);

    // x = segments@Wproj + bproj + dur*Wdur + bdur
    k_gemm<<<dim3(16,16),256,G_SMEM_BYTES>>>(segments, DIN_, Wproj, bproj, nullptr,
                                durations, Wdur, bdur, px, DD, DIN_, 0);

    for (int l=0; l<LAYERS; l++){
        size_t wdd = (size_t)l*DD*DD;
        k_ln<<<MROWS,256>>>(px, ln1g + l*DD, ln1b + l*DD, ph);

        k_gemm<<<dim3(16,16),256,G_SMEM_BYTES>>>(ph, DD, Wq + wdd, bq + l*DD, nullptr,
                                    nullptr,nullptr,nullptr, pq, DD, DD, 0);
        k_gemm<<<dim3(16,16),256,G_SMEM_BYTES>>>(ph, DD, Wk + wdd, bk + l*DD, nullptr,
                                    nullptr,nullptr,nullptr, pk, DD, DD, 0);
        k_gemm<<<dim3(16,16),256,G_SMEM_BYTES>>>(ph, DD, Wv + wdd, bv + l*DD, nullptr,
                                    nullptr,nullptr,nullptr, pv, DD, DD, 0);

        k_rope_apply<<<4096,256>>>(pq, pk, prc);

        k_scores<<<dim3(8,8,BB*HH),128>>>(pq, pk, pmask, psc);
        k_softmax<<<BB*HH*SQ,128>>>(psc);
        k_attnv<<<dim3(8,BB*HH),128>>>(psc, pv, pat);

        // x = x + attn@Wo + bo
        k_gemm<<<dim3(16,16),256,G_SMEM_BYTES>>>(pat, DD, Wo + wdd, bo + l*DD, px,
                                    nullptr,nullptr,nullptr, px, DD, DD, 0);

        k_ln<<<MROWS,256>>>(px, ln2g + l*DD, ln2b + l*DD, ph);

        // ffh = gelu(h@W1 + b1)
        k_gemm<<<dim3(64,16),256,G_SMEM_BYTES>>>(ph, DD, W1 + (size_t)l*DD*FF_, b1 + l*FF_, nullptr,
                                    nullptr,nullptr,nullptr, pfh, FF_, DD, 1);

        // x = x + ffh@W2 + b2   (last layer writes straight into d_out)
        float* outp = (l == LAYERS-1) ? (float*)d_out : px;
        k_gemm<<<dim3(16,16),256,G_SMEM_BYTES>>>(pfh, FF_, W2 + (size_t)l*FF_*DD, b2 + l*DD, px,
                                    nullptr,nullptr,nullptr, outp, DD, FF_, 0);
    }
}

// round 14
// speedup vs baseline: 2.3491x; 2.3153x over previous
#include <cuda_runtime.h>
#include <mma.h>
#include <cuda_fp16.h>
#include <cstdint>

using namespace nvcuda;

#define SQ   512
#define BB   4
#define DIN_ 768
#define DD   1024
#define HH   16
#define HDIM 64
#define FF_  4096
#define MROWS 2048   // S*B
#define LAYERS 12

// ---------------- device scratch (no allocs allowed) ----------------
__device__ float g_x   [MROWS*DD];
__device__ float g_h   [MROWS*DD];
__device__ float g_q   [MROWS*DD];
__device__ float g_k   [MROWS*DD];
__device__ float g_v   [MROWS*DD];
__device__ float g_attn[MROWS*DD];
__device__ float g_ffh [MROWS*FF_];
__device__ float g_scores[(size_t)BB*HH*SQ*SQ];
__device__ float g_rope[SQ*32*2];   // interleaved cos,sin per (s, j<32)
__device__ int   g_mask[BB*SQ];     // canonical 0/1 key mask

// ---------------- mask canonicalization (bool / int32 / float32 robust) ----
__global__ void k_mask_prep(const unsigned char* __restrict__ raw,
                            int* __restrict__ outm){
    __shared__ int s_float, s_bool;
    if (threadIdx.x==0){ s_float=0; s_bool=0; }
    __syncthreads();
    for (int i=threadIdx.x; i<BB*SQ; i+=256){
        unsigned char v = raw[i];
        if ((i&3)==3 && v==0x3f) atomicOr(&s_float,1);   // 1.0f byte pattern
        else if ((i&3)!=0 && v!=0) atomicOr(&s_bool,1);  // random bools
    }
    __syncthreads();
    int mode = s_float ? 2 : (s_bool ? 0 : 1); // 0=bool, 1=int32, 2=float32
    for (int i=threadIdx.x; i<BB*SQ; i+=256){
        int m;
        if (mode==0)      m = raw[i] != 0;
        else if (mode==1) m = ((const int*)raw)[i] != 0;
        else              m = ((const float*)raw)[i] != 0.f;
        outm[i] = m;
    }
}

// ---------------- RoPE cache ----------------
__global__ void k_rope_cache(float* __restrict__ cache){
    int i = blockIdx.x*blockDim.x + threadIdx.x;
    if (i >= SQ*32) return;
    int s = i >> 5, j = i & 31;
    float invf = powf(10000.f, -((float)(2*j)) / 64.f);
    float a = (float)s * invf;
    cache[2*i]   = cosf(a);
    cache[2*i+1] = sinf(a);
}

__global__ __launch_bounds__(256) void k_rope_apply(float* __restrict__ q,
                                                    float* __restrict__ k,
                                                    const float* __restrict__ cache){
    int i = blockIdx.x*256 + threadIdx.x;        // < 2048*16*32
    int j = i & 31;
    int h = (i >> 5) & 15;
    int r = i >> 9;                               // row = s*B+b
    int s = r >> 2;                               // B=4
    float c  = cache[(s*32+j)*2];
    float sn = cache[(s*32+j)*2+1];
    size_t base = (size_t)r*DD + h*HDIM;
    float a1 = q[base+j], a2 = q[base+j+32];
    q[base+j]    = a1*c - a2*sn;
    q[base+j+32] = a2*c + a1*sn;
    float b1 = k[base+j], b2 = k[base+j+32];
    k[base+j]    = b1*c - b2*sn;
    k[base+j+32] = b2*c + b1*sn;
}

// ---------------- LayerNorm ----------------
__global__ __launch_bounds__(256) void k_ln(const float* __restrict__ x,
                                            const float* __restrict__ g,
                                            const float* __restrict__ b,
                                            float* __restrict__ out){
    int row = blockIdx.x, tid = threadIdx.x;
    const float4* xr = (const float4*)(x + (size_t)row*DD);
    float4 v = xr[tid];
    float s  = v.x+v.y+v.z+v.w;
    float q2 = v.x*v.x+v.y*v.y+v.z*v.z+v.w*v.w;
    #pragma unroll
    for (int o=16;o;o>>=1){ s += __shfl_xor_sync(0xffffffffu,s,o);
                            q2 += __shfl_xor_sync(0xffffffffu,q2,o); }
    __shared__ float ss[8], sq[8];
    if ((tid&31)==0){ ss[tid>>5]=s; sq[tid>>5]=q2; }
    __syncthreads();
    float S_=0.f, Q_=0.f;
    #pragma unroll
    for (int i=0;i<8;i++){ S_+=ss[i]; Q_+=sq[i]; }
    float mean = S_ * (1.f/DD);
    float var  = Q_ * (1.f/DD) - mean*mean;
    float inv  = rsqrtf(var + 1e-5f);
    float4 gg = ((const float4*)g)[tid];
    float4 bb = ((const float4*)b)[tid];
    float4 o4;
    o4.x = (v.x-mean)*inv*gg.x + bb.x;
    o4.y = (v.y-mean)*inv*gg.y + bb.y;
    o4.z = (v.z-mean)*inv*gg.z + bb.z;
    o4.w = (v.w-mean)*inv*gg.w + bb.w;
    ((float4*)(out + (size_t)row*DD))[tid] = o4;
}

// split helper: v = hi + lo with hi = fp16(v), lo = fp16(v - hi)
__device__ __forceinline__ void h_split(float v, half& hi, half& lo){
    hi = __float2half_rn(v);
    lo = __float2half_rn(v - __half2float(hi));
}

// ======================================================================
// 3xFP16-split GEMM, double-buffered. C = epi(A[M,K] @ W[K,N])
// CTA tile 128x64, BK=16, 8 warps (4x2), warp tile 32x32 (2x2 of 16x16x16).
// smem per stage (half): Ah 128x24 | Al 128x24 | Bh 16x72 | Bl 16x72 = 8448 h
// two stages = 33792 B; epilogue aliases 8 x (32x36 float) = 36864 B.
// ======================================================================
#define GA 24
#define GB 72
#define STAGEH 8448

__global__ __launch_bounds__(256) void k_gemm(
    const float* __restrict__ A, int lda,
    const float* __restrict__ W,
    const float* __restrict__ bias,
    const float* __restrict__ residual,
    const float* __restrict__ rowscale,   // durations (per-row scalar) or null
    const float* __restrict__ colvec,     // Wdur
    const float* __restrict__ colbias,    // bdur
    float* __restrict__ C,
    int N, int K, int gelu)
{
    __shared__ __align__(16) unsigned char smraw[36864];
    half*  hs = (half*)smraw;
    float* fs = (float*)smraw;

    int tid = threadIdx.x, wid = tid>>5, lid = tid&31;
    int wm = wid & 3, wn = wid >> 2;
    int tile_n = blockIdx.x*64, tile_m = blockIdx.y*128;

    int ar0 = tid>>2,  ac = (tid&3)*4;      // A: 2 float4/thread
    int ar1 = ar0 + 64;
    int br  = tid>>4;  int bc = (tid&15)*4; // B: 1 float4/thread

    const float* Arow0 = A + (size_t)(tile_m+ar0)*lda + ac;
    const float* Arow1 = A + (size_t)(tile_m+ar1)*lda + ac;
    const float* Brow  = W + (size_t)br*N + tile_n + bc;

    wmma::fragment<wmma::accumulator,16,16,16,float> acc[2][2];
    #pragma unroll
    for (int i=0;i<2;i++)
        #pragma unroll
        for (int j=0;j<2;j++) wmma::fill_fragment(acc[i][j], 0.f);

    int nch = K >> 4;
    float4 ra0, ra1, rb;

    // prologue: chunk 0
    ra0 = *(const float4*)(Arow0);
    ra1 = *(const float4*)(Arow1);
    rb  = *(const float4*)(Brow);
    {
        half* AH = hs;         half* AL = hs + 3072;
        half* BH = hs + 6144;  half* BL = hs + 7296;
        half hi,lo;
        h_split(ra0.x,hi,lo); AH[ar0*GA+ac+0]=hi; AL[ar0*GA+ac+0]=lo;
        h_split(ra0.y,hi,lo); AH[ar0*GA+ac+1]=hi; AL[ar0*GA+ac+1]=lo;
        h_split(ra0.z,hi,lo); AH[ar0*GA+ac+2]=hi; AL[ar0*GA+ac+2]=lo;
        h_split(ra0.w,hi,lo); AH[ar0*GA+ac+3]=hi; AL[ar0*GA+ac+3]=lo;
        h_split(ra1.x,hi,lo); AH[ar1*GA+ac+0]=hi; AL[ar1*GA+ac+0]=lo;
        h_split(ra1.y,hi,lo); AH[ar1*GA+ac+1]=hi; AL[ar1*GA+ac+1]=lo;
        h_split(ra1.z,hi,lo); AH[ar1*GA+ac+2]=hi; AL[ar1*GA+ac+2]=lo;
        h_split(ra1.w,hi,lo); AH[ar1*GA+ac+3]=hi; AL[ar1*GA+ac+3]=lo;
        h_split(rb.x,hi,lo);  BH[br*GB+bc+0]=hi;  BL[br*GB+bc+0]=lo;
        h_split(rb.y,hi,lo);  BH[br*GB+bc+1]=hi;  BL[br*GB+bc+1]=lo;
        h_split(rb.z,hi,lo);  BH[br*GB+bc+2]=hi;  BL[br*GB+bc+2]=lo;
        h_split(rb.w,hi,lo);  BH[br*GB+bc+3]=hi;  BL[br*GB+bc+3]=lo;
    }
    __syncthreads();

    for (int ch=0; ch<nch; ch++){
        int cur = ch & 1;
        if (ch+1 < nch){
            int k0 = (ch+1)<<4;
            ra0 = *(const float4*)(Arow0 + k0);
            ra1 = *(const float4*)(Arow1 + k0);
            rb  = *(const float4*)(Brow  + (size_t)k0*N);
        }
        {
            half* AH = hs + cur*STAGEH;
            half* AL = AH + 3072;
            half* BH = AH + 6144;
            half* BL = AH + 7296;
            wmma::fragment<wmma::matrix_a,16,16,16,half,wmma::row_major> ah[2], al[2];
            wmma::fragment<wmma::matrix_b,16,16,16,half,wmma::row_major> bh[2], bl[2];
            wmma::load_matrix_sync(ah[0], AH + (wm*32   )*GA, GA);
            wmma::load_matrix_sync(ah[1], AH + (wm*32+16)*GA, GA);
            wmma::load_matrix_sync(al[0], AL + (wm*32   )*GA, GA);
            wmma::load_matrix_sync(al[1], AL + (wm*32+16)*GA, GA);
            wmma::load_matrix_sync(bh[0], BH + wn*32,         GB);
            wmma::load_matrix_sync(bh[1], BH + wn*32+16,      GB);
            wmma::load_matrix_sync(bl[0], BL + wn*32,         GB);
            wmma::load_matrix_sync(bl[1], BL + wn*32+16,      GB);
            #pragma unroll
            for (int i=0;i<2;i++)
                #pragma unroll
                for (int j=0;j<2;j++){
                    wmma::mma_sync(acc[i][j], ah[i], bl[j], acc[i][j]);
                    wmma::mma_sync(acc[i][j], al[i], bh[j], acc[i][j]);
                    wmma::mma_sync(acc[i][j], ah[i], bh[j], acc[i][j]);
                }
        }
        if (ch+1 < nch){
            half* AH = hs + (cur^1)*STAGEH;
            half* AL = AH + 3072;
            half* BH = AH + 6144;
            half* BL = AH + 7296;
            half hi,lo;
            h_split(ra0.x,hi,lo); AH[ar0*GA+ac+0]=hi; AL[ar0*GA+ac+0]=lo;
            h_split(ra0.y,hi,lo); AH[ar0*GA+ac+1]=hi; AL[ar0*GA+ac+1]=lo;
            h_split(ra0.z,hi,lo); AH[ar0*GA+ac+2]=hi; AL[ar0*GA+ac+2]=lo;
            h_split(ra0.w,hi,lo); AH[ar0*GA+ac+3]=hi; AL[ar0*GA+ac+3]=lo;
            h_split(ra1.x,hi,lo); AH[ar1*GA+ac+0]=hi; AL[ar1*GA+ac+0]=lo;
            h_split(ra1.y,hi,lo); AH[ar1*GA+ac+1]=hi; AL[ar1*GA+ac+1]=lo;
            h_split(ra1.z,hi,lo); AH[ar1*GA+ac+2]=hi; AL[ar1*GA+ac+2]=lo;
            h_split(ra1.w,hi,lo); AH[ar1*GA+ac+3]=hi; AL[ar1*GA+ac+3]=lo;
            h_split(rb.x,hi,lo);  BH[br*GB+bc+0]=hi;  BL[br*GB+bc+0]=lo;
            h_split(rb.y,hi,lo);  BH[br*GB+bc+1]=hi;  BL[br*GB+bc+1]=lo;
            h_split(rb.z,hi,lo);  BH[br*GB+bc+2]=hi;  BL[br*GB+bc+2]=lo;
            h_split(rb.w,hi,lo);  BH[br*GB+bc+3]=hi;  BL[br*GB+bc+3]=lo;
        }
        __syncthreads();
    }

    // ---------------- epilogue: per-warp smem staging ----------------
    float* stg = fs + wid*1152;               // 32x36
    #pragma unroll
    for (int i=0;i<2;i++)
        #pragma unroll
        for (int j=0;j<2;j++)
            wmma::store_matrix_sync(stg + i*16*36 + j*16, acc[i][j], 36, wmma::mem_row_major);
    __syncwarp();

    #pragma unroll
    for (int t=0;t<8;t++){
        int idx = lid + t*32;                 // 256 float4 per warp (32x32)
        int r = idx>>3, c4 = idx&7;
        int gr = tile_m + wm*32 + r;
        int gc = tile_n + wn*32 + c4*4;
        float4 v = *(const float4*)(stg + r*36 + c4*4);
        if (bias){
            float4 bb = *(const float4*)(bias + gc);
            v.x+=bb.x; v.y+=bb.y; v.z+=bb.z; v.w+=bb.w;
        }
        if (rowscale){
            float rs = rowscale[gr];
            float4 cv = *(const float4*)(colvec + gc);
            float4 cb = *(const float4*)(colbias + gc);
            v.x += rs*cv.x + cb.x; v.y += rs*cv.y + cb.y;
            v.z += rs*cv.z + cb.z; v.w += rs*cv.w + cb.w;
        }
        if (gelu){
            v.x = 0.5f*v.x*(1.f + erff(v.x*0.70710678118f));
            v.y = 0.5f*v.y*(1.f + erff(v.y*0.70710678118f));
            v.z = 0.5f*v.z*(1.f + erff(v.z*0.70710678118f));
            v.w = 0.5f*v.w*(1.f + erff(v.w*0.70710678118f));
        }
        if (residual){
            float4 rr = *(const float4*)(residual + (size_t)gr*N + gc);
            v.x+=rr.x; v.y+=rr.y; v.z+=rr.z; v.w+=rr.w;
        }
        *(float4*)(C + (size_t)gr*N + gc) = v;
    }
}

// ---------------- scores = scale * Q·K^T, masked (3xFP16) ----------------
// grid (kt=8, qt=8, bh=64), block 128 (4 warps 2x2), tile 64x64, d chunks of 32
#define QS 40
__global__ __launch_bounds__(128) void k_scores(const float* __restrict__ qb,
                                                const float* __restrict__ kb,
                                                const int* __restrict__ mask,
                                                float* __restrict__ sc){
    __shared__ __align__(16) unsigned char smraw[20480];
    half*  hs = (half*)smraw;
    half* Qh = hs;          // 64x40
    half* Ql = hs + 2560;
    half* Kh = hs + 5120;
    half* Kl = hs + 7680;
    float (*Cs)[72] = (float(*)[72])smraw;

    int tid = threadIdx.x;
    int kt = blockIdx.x, qt = blockIdx.y, bh = blockIdx.z;
    int b = bh >> 4, h = bh & 15;
    int wid = tid>>5, wm = wid&1, wn = wid>>1;

    wmma::fragment<wmma::accumulator,16,16,16,float> acc[2][2];
    #pragma unroll
    for (int i=0;i<2;i++)
        #pragma unroll
        for (int j=0;j<2;j++) wmma::fill_fragment(acc[i][j], 0.f);

    for (int dc=0; dc<64; dc+=32){
        #pragma unroll
        for (int t=0;t<4;t++){
            int i = tid + t*128;
            int r = i>>3, c = (i&7)*4;
            float4 v  = *(const float4*)(qb + ((size_t)(qt*64+r)*BB + b)*DD + h*HDIM + dc + c);
            half hi,lo;
            h_split(v.x,hi,lo); Qh[r*QS+c+0]=hi; Ql[r*QS+c+0]=lo;
            h_split(v.y,hi,lo); Qh[r*QS+c+1]=hi; Ql[r*QS+c+1]=lo;
            h_split(v.z,hi,lo); Qh[r*QS+c+2]=hi; Ql[r*QS+c+2]=lo;
            h_split(v.w,hi,lo); Qh[r*QS+c+3]=hi; Ql[r*QS+c+3]=lo;
            float4 v2 = *(const float4*)(kb + ((size_t)(kt*64+r)*BB + b)*DD + h*HDIM + dc + c);
            h_split(v2.x,hi,lo); Kh[r*QS+c+0]=hi; Kl[r*QS+c+0]=lo;
            h_split(v2.y,hi,lo); Kh[r*QS+c+1]=hi; Kl[r*QS+c+1]=lo;
            h_split(v2.z,hi,lo); Kh[r*QS+c+2]=hi; Kl[r*QS+c+2]=lo;
            h_split(v2.w,hi,lo); Kh[r*QS+c+3]=hi; Kl[r*QS+c+3]=lo;
        }
        __syncthreads();
        #pragma unroll
        for (int kk=0; kk<32; kk+=16){
            wmma::fragment<wmma::matrix_a,16,16,16,half,wmma::row_major> ah[2], al[2];
            wmma::fragment<wmma::matrix_b,16,16,16,half,wmma::col_major> bh[2], bl[2];
            wmma::load_matrix_sync(ah[0], Qh + (wm*32   )*QS + kk, QS);
            wmma::load_matrix_sync(ah[1], Qh + (wm*32+16)*QS + kk, QS);
            wmma::load_matrix_sync(al[0], Ql + (wm*32   )*QS + kk, QS);
            wmma::load_matrix_sync(al[1], Ql + (wm*32+16)*QS + kk, QS);
            wmma::load_matrix_sync(bh[0], Kh + (wn*32   )*QS + kk, QS);
            wmma::load_matrix_sync(bh[1], Kh + (wn*32+16)*QS + kk, QS);
            wmma::load_matrix_sync(bl[0], Kl + (wn*32   )*QS + kk, QS);
            wmma::load_matrix_sync(bl[1], Kl + (wn*32+16)*QS + kk, QS);
            #pragma unroll
            for (int i=0;i<2;i++)
                #pragma unroll
                for (int j=0;j<2;j++){
                    wmma::mma_sync(acc[i][j], ah[i], bl[j], acc[i][j]);
                    wmma::mma_sync(acc[i][j], al[i], bh[j], acc[i][j]);
                    wmma::mma_sync(acc[i][j], ah[i], bh[j], acc[i][j]);
                }
        }
        __syncthreads();
    }
    #pragma unroll
    for (int i=0;i<2;i++)
        #pragma unroll
        for (int j=0;j<2;j++)
            wmma::store_matrix_sync(&Cs[wm*32+i*16][wn*32+j*16], acc[i][j], 72, wmma::mem_row_major);
    __syncthreads();

    float* out = sc + (size_t)bh*SQ*SQ;
    #pragma unroll
    for (int t=0;t<32;t++){
        int i = tid + t*128;
        int r = i>>6, c = i&63;
        int gk = kt*64 + c;
        float v = Cs[r][c]*0.125f;
        if (mask[b*SQ + gk]) v = -1e30f;
        out[(size_t)(qt*64+r)*SQ + gk] = v;
    }
}

// ---------------- row softmax over 512 ----------------
__global__ __launch_bounds__(128) void k_softmax(float* __restrict__ scores){
    size_t row = blockIdx.x;
    float4* p = (float4*)(scores + row*SQ);
    int tid = threadIdx.x;
    float4 v = p[tid];
    float m = fmaxf(fmaxf(v.x,v.y), fmaxf(v.z,v.w));
    #pragma unroll
    for (int o=16;o;o>>=1) m = fmaxf(m, __shfl_xor_sync(0xffffffffu,m,o));
    __shared__ float s1[4], s2[4];
    if ((tid&31)==0) s1[tid>>5] = m;
    __syncthreads();
    m = fmaxf(fmaxf(s1[0],s1[1]), fmaxf(s1[2],s1[3]));
    v.x = expf(v.x-m); v.y = expf(v.y-m); v.z = expf(v.z-m); v.w = expf(v.w-m);
    float s = v.x+v.y+v.z+v.w;
    #pragma unroll
    for (int o=16;o;o>>=1) s += __shfl_xor_sync(0xffffffffu,s,o);
    if ((tid&31)==0) s2[tid>>5] = s;
    __syncthreads();
    s = s2[0]+s2[1]+s2[2]+s2[3];
    float inv = 1.f/s;
    v.x*=inv; v.y*=inv; v.z*=inv; v.w*=inv;
    p[tid] = v;
}

// ---------------- attn = probs @ V (3xFP16) ----------------
// grid (qt=8, bh=64), block 128, tile 64x64, K=512 in 16 chunks of 32
__global__ __launch_bounds__(128) void k_attnv(const float* __restrict__ pr,
                                               const float* __restrict__ vb,
                                               float* __restrict__ at){
    __shared__ __align__(16) unsigned char smraw[19456];
    half*  hs = (half*)smraw;
    half* Ph = hs;           // 64x40
    half* Pl = hs + 2560;
    half* Vh = hs + 5120;    // 32x72
    half* Vl = hs + 7424;
    float (*Cs)[72] = (float(*)[72])smraw;

    int tid = threadIdx.x;
    int qt = blockIdx.x, bh = blockIdx.y;
    int b = bh >> 4, h = bh & 15;
    int wid = tid>>5, wm = wid&1, wn = wid>>1;

    wmma::fragment<wmma::accumulator,16,16,16,float> acc[2][2];
    #pragma unroll
    for (int i=0;i<2;i++)
        #pragma unroll
        for (int j=0;j<2;j++) wmma::fill_fragment(acc[i][j], 0.f);

    const float* prb = pr + (size_t)bh*SQ*SQ;
    for (int kc=0; kc<16; kc++){
        #pragma unroll
        for (int t=0;t<4;t++){
            int i = tid + t*128;
            int r = i>>3, c = (i&7)*4;
            float4 v = *(const float4*)(prb + (size_t)(qt*64+r)*SQ + kc*32 + c);
            half hi,lo;
            h_split(v.x,hi,lo); Ph[r*QS+c+0]=hi; Pl[r*QS+c+0]=lo;
            h_split(v.y,hi,lo); Ph[r*QS+c+1]=hi; Pl[r*QS+c+1]=lo;
            h_split(v.z,hi,lo); Ph[r*QS+c+2]=hi; Pl[r*QS+c+2]=lo;
            h_split(v.w,hi,lo); Ph[r*QS+c+3]=hi; Pl[r*QS+c+3]=lo;
            int r2 = i>>4, c2 = (i&15)*4;
            float4 v2 = *(const float4*)(vb + ((size_t)(kc*32+r2)*BB + b)*DD + h*HDIM + c2);
            h_split(v2.x,hi,lo); Vh[r2*GB+c2+0]=hi; Vl[r2*GB+c2+0]=lo;
            h_split(v2.y,hi,lo); Vh[r2*GB+c2+1]=hi; Vl[r2*GB+c2+1]=lo;
            h_split(v2.z,hi,lo); Vh[r2*GB+c2+2]=hi; Vl[r2*GB+c2+2]=lo;
            h_split(v2.w,hi,lo); Vh[r2*GB+c2+3]=hi; Vl[r2*GB+c2+3]=lo;
        }
        __syncthreads();
        #pragma unroll
        for (int kk=0; kk<32; kk+=16){
            wmma::fragment<wmma::matrix_a,16,16,16,half,wmma::row_major> ah[2], al[2];
            wmma::fragment<wmma::matrix_b,16,16,16,half,wmma::row_major> bh[2], bl[2];
            wmma::load_matrix_sync(ah[0], Ph + (wm*32   )*QS + kk, QS);
            wmma::load_matrix_sync(ah[1], Ph + (wm*32+16)*QS + kk, QS);
            wmma::load_matrix_sync(al[0], Pl + (wm*32   )*QS + kk, QS);
            wmma::load_matrix_sync(al[1], Pl + (wm*32+16)*QS + kk, QS);
            wmma::load_matrix_sync(bh[0], Vh + kk*GB + wn*32,      GB);
            wmma::load_matrix_sync(bh[1], Vh + kk*GB + wn*32+16,   GB);
            wmma::load_matrix_sync(bl[0], Vl + kk*GB + wn*32,      GB);
            wmma::load_matrix_sync(bl[1], Vl + kk*GB + wn*32+16,   GB);
            #pragma unroll
            for (int i=0;i<2;i++)
                #pragma unroll
                for (int j=0;j<2;j++){
                    wmma::mma_sync(acc[i][j], ah[i], bl[j], acc[i][j]);
                    wmma::mma_sync(acc[i][j], al[i], bh[j], acc[i][j]);
                    wmma::mma_sync(acc[i][j], ah[i], bh[j], acc[i][j]);
                }
        }
        __syncthreads();
    }
    #pragma unroll
    for (int i=0;i<2;i++)
        #pragma unroll
        for (int j=0;j<2;j++)
            wmma::store_matrix_sync(&Cs[wm*32+i*16][wn*32+j*16], acc[i][j], 72, wmma::mem_row_major);
    __syncthreads();
    #pragma unroll
    for (int t=0;t<32;t++){
        int i = tid + t*128;
        int r = i>>6, c = i&63;
        at[((size_t)(qt*64+r)*BB + b)*DD + h*HDIM + c] = Cs[r][c];
    }
}

// ---------------- host ----------------
extern "C" void kernel_launch(void* const* d_in, const int* in_sizes, int n_in,
                              void* d_out, int out_size){
    const float* segments  = (const float*)d_in[0];
    const float* durations = (const float*)d_in[1];
    const unsigned char* maskraw = (const unsigned char*)d_in[2];
    const float* Wproj = (const float*)d_in[3];
    const float* bproj = (const float*)d_in[4];
    const float* Wdur  = (const float*)d_in[5];
    const float* bdur  = (const float*)d_in[6];
    const float* ln1g  = (const float*)d_in[7];
    const float* ln1b  = (const float*)d_in[8];
    const float* Wq    = (const float*)d_in[9];
    const float* bq    = (const float*)d_in[10];
    const float* Wk    = (const float*)d_in[11];
    const float* bk    = (const float*)d_in[12];
    const float* Wv    = (const float*)d_in[13];
    const float* bv    = (const float*)d_in[14];
    const float* Wo    = (const float*)d_in[15];
    const float* bo    = (const float*)d_in[16];
    const float* ln2g  = (const float*)d_in[17];
    const float* ln2b  = (const float*)d_in[18];
    const float* W1    = (const float*)d_in[19];
    const float* b1    = (const float*)d_in[20];
    const float* W2    = (const float*)d_in[21];
    const float* b2    = (const float*)d_in[22];

    float *px,*ph,*pq,*pk,*pv,*pat,*pfh,*psc,*prc;
    int* pmask;
    cudaGetSymbolAddress((void**)&px,  g_x);
    cudaGetSymbolAddress((void**)&ph,  g_h);
    cudaGetSymbolAddress((void**)&pq,  g_q);
    cudaGetSymbolAddress((void**)&pk,  g_k);
    cudaGetSymbolAddress((void**)&pv,  g_v);
    cudaGetSymbolAddress((void**)&pat, g_attn);
    cudaGetSymbolAddress((void**)&pfh, g_ffh);
    cudaGetSymbolAddress((void**)&psc, g_scores);
    cudaGetSymbolAddress((void**)&prc, g_rope);
    cudaGetSymbolAddress((void**)&pmask, g_mask);

    k_mask_prep<<<1,256>>>(maskraw, pmask);
    k_rope_cache<<<64,256>>>(prc);

    // x = segments@Wproj + bproj + dur*Wdur + bdur
    k_gemm<<<dim3(16,16),256>>>(segments, DIN_, Wproj, bproj, nullptr,
                                durations, Wdur, bdur, px, DD, DIN_, 0);

    for (int l=0; l<LAYERS; l++){
        size_t wdd = (size_t)l*DD*DD;
        k_ln<<<MROWS,256>>>(px, ln1g + l*DD, ln1b + l*DD, ph);

        k_gemm<<<dim3(16,16),256>>>(ph, DD, Wq + wdd, bq + l*DD, nullptr,
                                    nullptr,nullptr,nullptr, pq, DD, DD, 0);
        k_gemm<<<dim3(16,16),256>>>(ph, DD, Wk + wdd, bk + l*DD, nullptr,
                                    nullptr,nullptr,nullptr, pk, DD, DD, 0);
        k_gemm<<<dim3(16,16),256>>>(ph, DD, Wv + wdd, bv + l*DD, nullptr,
                                    nullptr,nullptr,nullptr, pv, DD, DD, 0);

        k_rope_apply<<<4096,256>>>(pq, pk, prc);

        k_scores<<<dim3(8,8,BB*HH),128>>>(pq, pk, pmask, psc);
        k_softmax<<<BB*HH*SQ,128>>>(psc);
        k_attnv<<<dim3(8,BB*HH),128>>>(psc, pv, pat);

        // x = x + attn@Wo + bo
        k_gemm<<<dim3(16,16),256>>>(pat, DD, Wo + wdd, bo + l*DD, px,
                                    nullptr,nullptr,nullptr, px, DD, DD, 0);

        k_ln<<<MROWS,256>>>(px, ln2g + l*DD, ln2b + l*DD, ph);

        // ffh = gelu(h@W1 + b1)
        k_gemm<<<dim3(64,16),256>>>(ph, DD, W1 + (size_t)l*DD*FF_, b1 + l*FF_, nullptr,
                                    nullptr,nullptr,nullptr, pfh, FF_, DD, 1);

        // x = x + ffh@W2 + b2   (last layer writes straight into d_out)
        float* outp = (l == LAYERS-1) ? (float*)d_out : px;
        k_gemm<<<dim3(16,16),256>>>(pfh, FF_, W2 + (size_t)l*FF_*DD, b2 + l*DD, px,
                                    nullptr,nullptr,nullptr, outp, DD, FF_, 0);
    }
}

// round 15
// speedup vs baseline: 3.4079x; 1.4508x over previous
#include <cuda_runtime.h>
#include <mma.h>
#include <cuda_fp16.h>
#include <cstdint>

using namespace nvcuda;

#define SQ   512
#define BB   4
#define DIN_ 768
#define DD   1024
#define HH   16
#define HDIM 64
#define FF_  4096
#define MROWS 2048   // S*B
#define LAYERS 12

// ---------------- device scratch (no allocs allowed) ----------------
__device__ float g_x   [MROWS*DD];
__device__ float g_h   [MROWS*DD];
__device__ float g_q   [MROWS*DD];
__device__ float g_k   [MROWS*DD];
__device__ float g_v   [MROWS*DD];
__device__ float g_attn[MROWS*DD];
__device__ float g_ffh [MROWS*FF_];
__device__ float g_scores[(size_t)BB*HH*SQ*SQ];
__device__ float g_rope[SQ*32*2];   // interleaved cos,sin per (s, j<32)
__device__ int   g_mask[BB*SQ];     // canonical 0/1 key mask

// ---------------- mask canonicalization (bool / int32 / float32 robust) ----
__global__ void k_mask_prep(const unsigned char* __restrict__ raw,
                            int* __restrict__ outm){
    __shared__ int s_float, s_bool;
    if (threadIdx.x==0){ s_float=0; s_bool=0; }
    __syncthreads();
    for (int i=threadIdx.x; i<BB*SQ; i+=256){
        unsigned char v = raw[i];
        if ((i&3)==3 && v==0x3f) atomicOr(&s_float,1);   // 1.0f byte pattern
        else if ((i&3)!=0 && v!=0) atomicOr(&s_bool,1);  // random bools
    }
    __syncthreads();
    int mode = s_float ? 2 : (s_bool ? 0 : 1); // 0=bool, 1=int32, 2=float32
    for (int i=threadIdx.x; i<BB*SQ; i+=256){
        int m;
        if (mode==0)      m = raw[i] != 0;
        else if (mode==1) m = ((const int*)raw)[i] != 0;
        else              m = ((const float*)raw)[i] != 0.f;
        outm[i] = m;
    }
}

// ---------------- RoPE cache ----------------
__global__ void k_rope_cache(float* __restrict__ cache){
    int i = blockIdx.x*blockDim.x + threadIdx.x;
    if (i >= SQ*32) return;
    int s = i >> 5, j = i & 31;
    float invf = powf(10000.f, -((float)(2*j)) / 64.f);
    float a = (float)s * invf;
    cache[2*i]   = cosf(a);
    cache[2*i+1] = sinf(a);
}

__global__ __launch_bounds__(256) void k_rope_apply(float* __restrict__ q,
                                                    float* __restrict__ k,
                                                    const float* __restrict__ cache){
    int i = blockIdx.x*256 + threadIdx.x;        // < 2048*16*32
    int j = i & 31;
    int h = (i >> 5) & 15;
    int r = i >> 9;                               // row = s*B+b
    int s = r >> 2;                               // B=4
    float c  = cache[(s*32+j)*2];
    float sn = cache[(s*32+j)*2+1];
    size_t base = (size_t)r*DD + h*HDIM;
    float a1 = q[base+j], a2 = q[base+j+32];
    q[base+j]    = a1*c - a2*sn;
    q[base+j+32] = a2*c + a1*sn;
    float b1 = k[base+j], b2 = k[base+j+32];
    k[base+j]    = b1*c - b2*sn;
    k[base+j+32] = b2*c + b1*sn;
}

// ---------------- LayerNorm ----------------
__global__ __launch_bounds__(256) void k_ln(const float* __restrict__ x,
                                            const float* __restrict__ g,
                                            const float* __restrict__ b,
                                            float* __restrict__ out){
    int row = blockIdx.x, tid = threadIdx.x;
    const float4* xr = (const float4*)(x + (size_t)row*DD);
    float4 v = xr[tid];
    float s  = v.x+v.y+v.z+v.w;
    float q2 = v.x*v.x+v.y*v.y+v.z*v.z+v.w*v.w;
    #pragma unroll
    for (int o=16;o;o>>=1){ s += __shfl_xor_sync(0xffffffffu,s,o);
                            q2 += __shfl_xor_sync(0xffffffffu,q2,o); }
    __shared__ float ss[8], sq[8];
    if ((tid&31)==0){ ss[tid>>5]=s; sq[tid>>5]=q2; }
    __syncthreads();
    float S_=0.f, Q_=0.f;
    #pragma unroll
    for (int i=0;i<8;i++){ S_+=ss[i]; Q_+=sq[i]; }
    float mean = S_ * (1.f/DD);
    float var  = Q_ * (1.f/DD) - mean*mean;
    float inv  = rsqrtf(var + 1e-5f);
    float4 gg = ((const float4*)g)[tid];
    float4 bb = ((const float4*)b)[tid];
    float4 o4;
    o4.x = (v.x-mean)*inv*gg.x + bb.x;
    o4.y = (v.y-mean)*inv*gg.y + bb.y;
    o4.z = (v.z-mean)*inv*gg.z + bb.z;
    o4.w = (v.w-mean)*inv*gg.w + bb.w;
    ((float4*)(out + (size_t)row*DD))[tid] = o4;
}

// split helper: v = hi + lo with hi = fp16(v), lo = fp16(v - hi)
__device__ __forceinline__ void h_split(float v, half& hi, half& lo){
    hi = __float2half_rn(v);
    lo = __float2half_rn(v - __half2float(hi));
}

// ======================================================================
// 3xFP16-split GEMM, double-buffered. C = epi(A[M,K] @ W[K,N])
// CTA tile 128x128, BK=16, 8 warps (4x2), warp tile 32x64.
// smem/stage (half): AH 128x24 | AL 128x24 | BH 16x136 | BL 16x136
//   = 10496 halves = 20992 B; 2 stages = 41984 B (static).
// Epilogue aliases 8 x (32x36 float) = 36864 B, two 32-col passes.
// ======================================================================
#define GA  24
#define GBN 136
#define STAGEH 10496

__global__ __launch_bounds__(256,1) void k_gemm(
    const float* __restrict__ A, int lda,
    const float* __restrict__ W,
    const float* __restrict__ bias,
    const float* __restrict__ residual,
    const float* __restrict__ rowscale,   // durations (per-row scalar) or null
    const float* __restrict__ colvec,     // Wdur
    const float* __restrict__ colbias,    // bdur
    float* __restrict__ C,
    int N, int K, int gelu)
{
    __shared__ __align__(16) unsigned char smraw[41984];
    half*  hs = (half*)smraw;
    float* fs = (float*)smraw;

    int tid = threadIdx.x, wid = tid>>5, lid = tid&31;
    int wm = wid & 3, wn = wid >> 2;
    int tile_n = blockIdx.x*128, tile_m = blockIdx.y*128;

    int ar0 = tid>>2,  ac = (tid&3)*4;      // A: 2 float4/thread
    int ar1 = ar0 + 64;
    int br  = tid>>4;  int bc = (tid&15)*4; // B: 2 float4/thread (cols bc, bc+64)

    const float* Arow0 = A + (size_t)(tile_m+ar0)*lda + ac;
    const float* Arow1 = A + (size_t)(tile_m+ar1)*lda + ac;
    const float* Brow  = W + (size_t)br*N + tile_n + bc;

    wmma::fragment<wmma::accumulator,16,16,16,float> acc[2][4];
    #pragma unroll
    for (int i=0;i<2;i++)
        #pragma unroll
        for (int j=0;j<4;j++) wmma::fill_fragment(acc[i][j], 0.f);

    int nch = K >> 4;
    float4 ra0, ra1, rb0, rb1;

    // prologue: chunk 0 -> stage 0
    ra0 = *(const float4*)(Arow0);
    ra1 = *(const float4*)(Arow1);
    rb0 = *(const float4*)(Brow);
    rb1 = *(const float4*)(Brow + 64);
    {
        half* AH = hs;          half* AL = hs + 3072;
        half* BH = hs + 6144;   half* BL = hs + 8320;
        half hi,lo;
        h_split(ra0.x,hi,lo); AH[ar0*GA+ac+0]=hi; AL[ar0*GA+ac+0]=lo;
        h_split(ra0.y,hi,lo); AH[ar0*GA+ac+1]=hi; AL[ar0*GA+ac+1]=lo;
        h_split(ra0.z,hi,lo); AH[ar0*GA+ac+2]=hi; AL[ar0*GA+ac+2]=lo;
        h_split(ra0.w,hi,lo); AH[ar0*GA+ac+3]=hi; AL[ar0*GA+ac+3]=lo;
        h_split(ra1.x,hi,lo); AH[ar1*GA+ac+0]=hi; AL[ar1*GA+ac+0]=lo;
        h_split(ra1.y,hi,lo); AH[ar1*GA+ac+1]=hi; AL[ar1*GA+ac+1]=lo;
        h_split(ra1.z,hi,lo); AH[ar1*GA+ac+2]=hi; AL[ar1*GA+ac+2]=lo;
        h_split(ra1.w,hi,lo); AH[ar1*GA+ac+3]=hi; AL[ar1*GA+ac+3]=lo;
        h_split(rb0.x,hi,lo); BH[br*GBN+bc+0]=hi; BL[br*GBN+bc+0]=lo;
        h_split(rb0.y,hi,lo); BH[br*GBN+bc+1]=hi; BL[br*GBN+bc+1]=lo;
        h_split(rb0.z,hi,lo); BH[br*GBN+bc+2]=hi; BL[br*GBN+bc+2]=lo;
        h_split(rb0.w,hi,lo); BH[br*GBN+bc+3]=hi; BL[br*GBN+bc+3]=lo;
        h_split(rb1.x,hi,lo); BH[br*GBN+bc+64]=hi; BL[br*GBN+bc+64]=lo;
        h_split(rb1.y,hi,lo); BH[br*GBN+bc+65]=hi; BL[br*GBN+bc+65]=lo;
        h_split(rb1.z,hi,lo); BH[br*GBN+bc+66]=hi; BL[br*GBN+bc+66]=lo;
        h_split(rb1.w,hi,lo); BH[br*GBN+bc+67]=hi; BL[br*GBN+bc+67]=lo;
    }
    __syncthreads();

    for (int ch=0; ch<nch; ch++){
        int cur = ch & 1;
        if (ch+1 < nch){
            int k0 = (ch+1)<<4;
            ra0 = *(const float4*)(Arow0 + k0);
            ra1 = *(const float4*)(Arow1 + k0);
            rb0 = *(const float4*)(Brow  + (size_t)k0*N);
            rb1 = *(const float4*)(Brow  + (size_t)k0*N + 64);
        }
        {
            half* AH = hs + cur*STAGEH;
            half* AL = AH + 3072;
            half* BH = AH + 6144;
            half* BL = AH + 8320;
            wmma::fragment<wmma::matrix_a,16,16,16,half,wmma::row_major> ah[2], al[2];
            wmma::fragment<wmma::matrix_b,16,16,16,half,wmma::row_major> bh[4], bl[4];
            #pragma unroll
            for (int i=0;i<2;i++){
                wmma::load_matrix_sync(ah[i], AH + (wm*32+i*16)*GA, GA);
                wmma::load_matrix_sync(al[i], AL + (wm*32+i*16)*GA, GA);
            }
            #pragma unroll
            for (int j=0;j<4;j++){
                wmma::load_matrix_sync(bh[j], BH + wn*64 + j*16, GBN);
                wmma::load_matrix_sync(bl[j], BL + wn*64 + j*16, GBN);
            }
            #pragma unroll
            for (int i=0;i<2;i++)
                #pragma unroll
                for (int j=0;j<4;j++){
                    wmma::mma_sync(acc[i][j], ah[i], bl[j], acc[i][j]);
                    wmma::mma_sync(acc[i][j], al[i], bh[j], acc[i][j]);
                    wmma::mma_sync(acc[i][j], ah[i], bh[j], acc[i][j]);
                }
        }
        if (ch+1 < nch){
            half* AH = hs + (cur^1)*STAGEH;
            half* AL = AH + 3072;
            half* BH = AH + 6144;
            half* BL = AH + 8320;
            half hi,lo;
            h_split(ra0.x,hi,lo); AH[ar0*GA+ac+0]=hi; AL[ar0*GA+ac+0]=lo;
            h_split(ra0.y,hi,lo); AH[ar0*GA+ac+1]=hi; AL[ar0*GA+ac+1]=lo;
            h_split(ra0.z,hi,lo); AH[ar0*GA+ac+2]=hi; AL[ar0*GA+ac+2]=lo;
            h_split(ra0.w,hi,lo); AH[ar0*GA+ac+3]=hi; AL[ar0*GA+ac+3]=lo;
            h_split(ra1.x,hi,lo); AH[ar1*GA+ac+0]=hi; AL[ar1*GA+ac+0]=lo;
            h_split(ra1.y,hi,lo); AH[ar1*GA+ac+1]=hi; AL[ar1*GA+ac+1]=lo;
            h_split(ra1.z,hi,lo); AH[ar1*GA+ac+2]=hi; AL[ar1*GA+ac+2]=lo;
            h_split(ra1.w,hi,lo); AH[ar1*GA+ac+3]=hi; AL[ar1*GA+ac+3]=lo;
            h_split(rb0.x,hi,lo); BH[br*GBN+bc+0]=hi; BL[br*GBN+bc+0]=lo;
            h_split(rb0.y,hi,lo); BH[br*GBN+bc+1]=hi; BL[br*GBN+bc+1]=lo;
            h_split(rb0.z,hi,lo); BH[br*GBN+bc+2]=hi; BL[br*GBN+bc+2]=lo;
            h_split(rb0.w,hi,lo); BH[br*GBN+bc+3]=hi; BL[br*GBN+bc+3]=lo;
            h_split(rb1.x,hi,lo); BH[br*GBN+bc+64]=hi; BL[br*GBN+bc+64]=lo;
            h_split(rb1.y,hi,lo); BH[br*GBN+bc+65]=hi; BL[br*GBN+bc+65]=lo;
            h_split(rb1.z,hi,lo); BH[br*GBN+bc+66]=hi; BL[br*GBN+bc+66]=lo;
            h_split(rb1.w,hi,lo); BH[br*GBN+bc+67]=hi; BL[br*GBN+bc+67]=lo;
        }
        __syncthreads();
    }

    // ---------------- epilogue: per-warp smem staging, two 32-col passes ----
    float* stg = fs + wid*1152;               // 32x36 floats per warp
    #pragma unroll
    for (int p=0;p<2;p++){
        __syncwarp();
        #pragma unroll
        for (int i=0;i<2;i++)
            #pragma unroll
            for (int j=0;j<2;j++)
                wmma::store_matrix_sync(stg + i*16*36 + j*16, acc[i][p*2+j], 36, wmma::mem_row_major);
        __syncwarp();
        #pragma unroll
        for (int t=0;t<8;t++){
            int idx = lid + t*32;             // 256 float4 per warp (32x32)
            int r = idx>>3, c4 = idx&7;
            int gr = tile_m + wm*32 + r;
            int gc = tile_n + wn*64 + p*32 + c4*4;
            float4 v = *(const float4*)(stg + r*36 + c4*4);
            if (bias){
                float4 bb = *(const float4*)(bias + gc);
                v.x+=bb.x; v.y+=bb.y; v.z+=bb.z; v.w+=bb.w;
            }
            if (rowscale){
                float rs = rowscale[gr];
                float4 cv = *(const float4*)(colvec + gc);
                float4 cb = *(const float4*)(colbias + gc);
                v.x += rs*cv.x + cb.x; v.y += rs*cv.y + cb.y;
                v.z += rs*cv.z + cb.z; v.w += rs*cv.w + cb.w;
            }
            if (gelu){
                v.x = 0.5f*v.x*(1.f + erff(v.x*0.70710678118f));
                v.y = 0.5f*v.y*(1.f + erff(v.y*0.70710678118f));
                v.z = 0.5f*v.z*(1.f + erff(v.z*0.70710678118f));
                v.w = 0.5f*v.w*(1.f + erff(v.w*0.70710678118f));
            }
            if (residual){
                float4 rr = *(const float4*)(residual + (size_t)gr*N + gc);
                v.x+=rr.x; v.y+=rr.y; v.z+=rr.z; v.w+=rr.w;
            }
            *(float4*)(C + (size_t)gr*N + gc) = v;
        }
    }
}

// ---------------- scores = scale * Q·K^T, masked (3xFP16) ----------------
// grid (kt=8, qt=8, bh=64), block 128 (4 warps 2x2), tile 64x64, d chunks of 32
#define QS 40
#define GB 72
__global__ __launch_bounds__(128) void k_scores(const float* __restrict__ qb,
                                                const float* __restrict__ kb,
                                                const int* __restrict__ mask,
                                                float* __restrict__ sc){
    __shared__ __align__(16) unsigned char smraw[20480];
    half*  hs = (half*)smraw;
    half* Qh = hs;          // 64x40
    half* Ql = hs + 2560;
    half* Kh = hs + 5120;
    half* Kl = hs + 7680;
    float (*Cs)[72] = (float(*)[72])smraw;

    int tid = threadIdx.x;
    int kt = blockIdx.x, qt = blockIdx.y, bh = blockIdx.z;
    int b = bh >> 4, h = bh & 15;
    int wid = tid>>5, wm = wid&1, wn = wid>>1;

    wmma::fragment<wmma::accumulator,16,16,16,float> acc[2][2];
    #pragma unroll
    for (int i=0;i<2;i++)
        #pragma unroll
        for (int j=0;j<2;j++) wmma::fill_fragment(acc[i][j], 0.f);

    for (int dc=0; dc<64; dc+=32){
        #pragma unroll
        for (int t=0;t<4;t++){
            int i = tid + t*128;
            int r = i>>3, c = (i&7)*4;
            float4 v  = *(const float4*)(qb + ((size_t)(qt*64+r)*BB + b)*DD + h*HDIM + dc + c);
            half hi,lo;
            h_split(v.x,hi,lo); Qh[r*QS+c+0]=hi; Ql[r*QS+c+0]=lo;
            h_split(v.y,hi,lo); Qh[r*QS+c+1]=hi; Ql[r*QS+c+1]=lo;
            h_split(v.z,hi,lo); Qh[r*QS+c+2]=hi; Ql[r*QS+c+2]=lo;
            h_split(v.w,hi,lo); Qh[r*QS+c+3]=hi; Ql[r*QS+c+3]=lo;
            float4 v2 = *(const float4*)(kb + ((size_t)(kt*64+r)*BB + b)*DD + h*HDIM + dc + c);
            h_split(v2.x,hi,lo); Kh[r*QS+c+0]=hi; Kl[r*QS+c+0]=lo;
            h_split(v2.y,hi,lo); Kh[r*QS+c+1]=hi; Kl[r*QS+c+1]=lo;
            h_split(v2.z,hi,lo); Kh[r*QS+c+2]=hi; Kl[r*QS+c+2]=lo;
            h_split(v2.w,hi,lo); Kh[r*QS+c+3]=hi; Kl[r*QS+c+3]=lo;
        }
        __syncthreads();
        #pragma unroll
        for (int kk=0; kk<32; kk+=16){
            wmma::fragment<wmma::matrix_a,16,16,16,half,wmma::row_major> ah[2], al[2];
            wmma::fragment<wmma::matrix_b,16,16,16,half,wmma::col_major> bh[2], bl[2];
            wmma::load_matrix_sync(ah[0], Qh + (wm*32   )*QS + kk, QS);
            wmma::load_matrix_sync(ah[1], Qh + (wm*32+16)*QS + kk, QS);
            wmma::load_matrix_sync(al[0], Ql + (wm*32   )*QS + kk, QS);
            wmma::load_matrix_sync(al[1], Ql + (wm*32+16)*QS + kk, QS);
            wmma::load_matrix_sync(bh[0], Kh + (wn*32   )*QS + kk, QS);
            wmma::load_matrix_sync(bh[1], Kh + (wn*32+16)*QS + kk, QS);
            wmma::load_matrix_sync(bl[0], Kl + (wn*32   )*QS + kk, QS);
            wmma::load_matrix_sync(bl[1], Kl + (wn*32+16)*QS + kk, QS);
            #pragma unroll
            for (int i=0;i<2;i++)
                #pragma unroll
                for (int j=0;j<2;j++){
                    wmma::mma_sync(acc[i][j], ah[i], bl[j], acc[i][j]);
                    wmma::mma_sync(acc[i][j], al[i], bh[j], acc[i][j]);
                    wmma::mma_sync(acc[i][j], ah[i], bh[j], acc[i][j]);
                }
        }
        __syncthreads();
    }
    #pragma unroll
    for (int i=0;i<2;i++)
        #pragma unroll
        for (int j=0;j<2;j++)
            wmma::store_matrix_sync(&Cs[wm*32+i*16][wn*32+j*16], acc[i][j], 72, wmma::mem_row_major);
    __syncthreads();

    float* out = sc + (size_t)bh*SQ*SQ;
    #pragma unroll
    for (int t=0;t<32;t++){
        int i = tid + t*128;
        int r = i>>6, c = i&63;
        int gk = kt*64 + c;
        float v = Cs[r][c]*0.125f;
        if (mask[b*SQ + gk]) v = -1e30f;
        out[(size_t)(qt*64+r)*SQ + gk] = v;
    }
}

// ---------------- row softmax over 512 ----------------
__global__ __launch_bounds__(128) void k_softmax(float* __restrict__ scores){
    size_t row = blockIdx.x;
    float4* p = (float4*)(scores + row*SQ);
    int tid = threadIdx.x;
    float4 v = p[tid];
    float m = fmaxf(fmaxf(v.x,v.y), fmaxf(v.z,v.w));
    #pragma unroll
    for (int o=16;o;o>>=1) m = fmaxf(m, __shfl_xor_sync(0xffffffffu,m,o));
    __shared__ float s1[4], s2[4];
    if ((tid&31)==0) s1[tid>>5] = m;
    __syncthreads();
    m = fmaxf(fmaxf(s1[0],s1[1]), fmaxf(s1[2],s1[3]));
    v.x = expf(v.x-m); v.y = expf(v.y-m); v.z = expf(v.z-m); v.w = expf(v.w-m);
    float s = v.x+v.y+v.z+v.w;
    #pragma unroll
    for (int o=16;o;o>>=1) s += __shfl_xor_sync(0xffffffffu,s,o);
    if ((tid&31)==0) s2[tid>>5] = s;
    __syncthreads();
    s = s2[0]+s2[1]+s2[2]+s2[3];
    float inv = 1.f/s;
    v.x*=inv; v.y*=inv; v.z*=inv; v.w*=inv;
    p[tid] = v;
}

// ---------------- attn = probs @ V (3xFP16) ----------------
// grid (qt=8, bh=64), block 128, tile 64x64, K=512 in 16 chunks of 32
__global__ __launch_bounds__(128) void k_attnv(const float* __restrict__ pr,
                                               const float* __restrict__ vb,
                                               float* __restrict__ at){
    __shared__ __align__(16) unsigned char smraw[19456];
    half*  hs = (half*)smraw;
    half* Ph = hs;           // 64x40
    half* Pl = hs + 2560;
    half* Vh = hs + 5120;    // 32x72
    half* Vl = hs + 7424;
    float (*Cs)[72] = (float(*)[72])smraw;

    int tid = threadIdx.x;
    int qt = blockIdx.x, bh = blockIdx.y;
    int b = bh >> 4, h = bh & 15;
    int wid = tid>>5, wm = wid&1, wn = wid>>1;

    wmma::fragment<wmma::accumulator,16,16,16,float> acc[2][2];
    #pragma unroll
    for (int i=0;i<2;i++)
        #pragma unroll
        for (int j=0;j<2;j++) wmma::fill_fragment(acc[i][j], 0.f);

    const float* prb = pr + (size_t)bh*SQ*SQ;
    for (int kc=0; kc<16; kc++){
        #pragma unroll
        for (int t=0;t<4;t++){
            int i = tid + t*128;
            int r = i>>3, c = (i&7)*4;
            float4 v = *(const float4*)(prb + (size_t)(qt*64+r)*SQ + kc*32 + c);
            half hi,lo;
            h_split(v.x,hi,lo); Ph[r*QS+c+0]=hi; Pl[r*QS+c+0]=lo;
            h_split(v.y,hi,lo); Ph[r*QS+c+1]=hi; Pl[r*QS+c+1]=lo;
            h_split(v.z,hi,lo); Ph[r*QS+c+2]=hi; Pl[r*QS+c+2]=lo;
            h_split(v.w,hi,lo); Ph[r*QS+c+3]=hi; Pl[r*QS+c+3]=lo;
            int r2 = i>>4, c2 = (i&15)*4;
            float4 v2 = *(const float4*)(vb + ((size_t)(kc*32+r2)*BB + b)*DD + h*HDIM + c2);
            h_split(v2.x,hi,lo); Vh[r2*GB+c2+0]=hi; Vl[r2*GB+c2+0]=lo;
            h_split(v2.y,hi,lo); Vh[r2*GB+c2+1]=hi; Vl[r2*GB+c2+1]=lo;
            h_split(v2.z,hi,lo); Vh[r2*GB+c2+2]=hi; Vl[r2*GB+c2+2]=lo;
            h_split(v2.w,hi,lo); Vh[r2*GB+c2+3]=hi; Vl[r2*GB+c2+3]=lo;
        }
        __syncthreads();
        #pragma unroll
        for (int kk=0; kk<32; kk+=16){
            wmma::fragment<wmma::matrix_a,16,16,16,half,wmma::row_major> ah[2], al[2];
            wmma::fragment<wmma::matrix_b,16,16,16,half,wmma::row_major> bh[2], bl[2];
            wmma::load_matrix_sync(ah[0], Ph + (wm*32   )*QS + kk, QS);
            wmma::load_matrix_sync(ah[1], Ph + (wm*32+16)*QS + kk, QS);
            wmma::load_matrix_sync(al[0], Pl + (wm*32   )*QS + kk, QS);
            wmma::load_matrix_sync(al[1], Pl + (wm*32+16)*QS + kk, QS);
            wmma::load_matrix_sync(bh[0], Vh + kk*GB + wn*32,      GB);
            wmma::load_matrix_sync(bh[1], Vh + kk*GB + wn*32+16,   GB);
            wmma::load_matrix_sync(bl[0], Vl + kk*GB + wn*32,      GB);
            wmma::load_matrix_sync(bl[1], Vl + kk*GB + wn*32+16,   GB);
            #pragma unroll
            for (int i=0;i<2;i++)
                #pragma unroll
                for (int j=0;j<2;j++){
                    wmma::mma_sync(acc[i][j], ah[i], bl[j], acc[i][j]);
                    wmma::mma_sync(acc[i][j], al[i], bh[j], acc[i][j]);
                    wmma::mma_sync(acc[i][j], ah[i], bh[j], acc[i][j]);
                }
        }
        __syncthreads();
    }
    #pragma unroll
    for (int i=0;i<2;i++)
        #pragma unroll
        for (int j=0;j<2;j++)
            wmma::store_matrix_sync(&Cs[wm*32+i*16][wn*32+j*16], acc[i][j], 72, wmma::mem_row_major);
    __syncthreads();
    #pragma unroll
    for (int t=0;t<32;t++){
        int i = tid + t*128;
        int r = i>>6, c = i&63;
        at[((size_t)(qt*64+r)*BB + b)*DD + h*HDIM + c] = Cs[r][c];
    }
}

// ---------------- host ----------------
extern "C" void kernel_launch(void* const* d_in, const int* in_sizes, int n_in,
                              void* d_out, int out_size){
    const float* segments  = (const float*)d_in[0];
    const float* durations = (const float*)d_in[1];
    const unsigned char* maskraw = (const unsigned char*)d_in[2];
    const float* Wproj = (const float*)d_in[3];
    const float* bproj = (const float*)d_in[4];
    const float* Wdur  = (const float*)d_in[5];
    const float* bdur  = (const float*)d_in[6];
    const float* ln1g  = (const float*)d_in[7];
    const float* ln1b  = (const float*)d_in[8];
    const float* Wq    = (const float*)d_in[9];
    const float* bq    = (const float*)d_in[10];
    const float* Wk    = (const float*)d_in[11];
    const float* bk    = (const float*)d_in[12];
    const float* Wv    = (const float*)d_in[13];
    const float* bv    = (const float*)d_in[14];
    const float* Wo    = (const float*)d_in[15];
    const float* bo    = (const float*)d_in[16];
    const float* ln2g  = (const float*)d_in[17];
    const float* ln2b  = (const float*)d_in[18];
    const float* W1    = (const float*)d_in[19];
    const float* b1    = (const float*)d_in[20];
    const float* W2    = (const float*)d_in[21];
    const float* b2    = (const float*)d_in[22];

    float *px,*ph,*pq,*pk,*pv,*pat,*pfh,*psc,*prc;
    int* pmask;
    cudaGetSymbolAddress((void**)&px,  g_x);
    cudaGetSymbolAddress((void**)&ph,  g_h);
    cudaGetSymbolAddress((void**)&pq,  g_q);
    cudaGetSymbolAddress((void**)&pk,  g_k);
    cudaGetSymbolAddress((void**)&pv,  g_v);
    cudaGetSymbolAddress((void**)&pat, g_attn);
    cudaGetSymbolAddress((void**)&pfh, g_ffh);
    cudaGetSymbolAddress((void**)&psc, g_scores);
    cudaGetSymbolAddress((void**)&prc, g_rope);
    cudaGetSymbolAddress((void**)&pmask, g_mask);

    k_mask_prep<<<1,256>>>(maskraw, pmask);
    k_rope_cache<<<64,256>>>(prc);

    // x = segments@Wproj + bproj + dur*Wdur + bdur
    k_gemm<<<dim3(8,16),256>>>(segments, DIN_, Wproj, bproj, nullptr,
                                durations, Wdur, bdur, px, DD, DIN_, 0);

    for (int l=0; l<LAYERS; l++){
        size_t wdd = (size_t)l*DD*DD;
        k_ln<<<MROWS,256>>>(px, ln1g + l*DD, ln1b + l*DD, ph);

        k_gemm<<<dim3(8,16),256>>>(ph, DD, Wq + wdd, bq + l*DD, nullptr,
                                    nullptr,nullptr,nullptr, pq, DD, DD, 0);
        k_gemm<<<dim3(8,16),256>>>(ph, DD, Wk + wdd, bk + l*DD, nullptr,
                                    nullptr,nullptr,nullptr, pk, DD, DD, 0);
        k_gemm<<<dim3(8,16),256>>>(ph, DD, Wv + wdd, bv + l*DD, nullptr,
                                    nullptr,nullptr,nullptr, pv, DD, DD, 0);

        k_rope_apply<<<4096,256>>>(pq, pk, prc);

        k_scores<<<dim3(8,8,BB*HH),128>>>(pq, pk, pmask, psc);
        k_softmax<<<BB*HH*SQ,128>>>(psc);
        k_attnv<<<dim3(8,BB*HH),128>>>(psc, pv, pat);

        // x = x + attn@Wo + bo
        k_gemm<<<dim3(8,16),256>>>(pat, DD, Wo + wdd, bo + l*DD, px,
                                    nullptr,nullptr,nullptr, px, DD, DD, 0);

        k_ln<<<MROWS,256>>>(px, ln2g + l*DD, ln2b + l*DD, ph);

        // ffh = gelu(h@W1 + b1)
        k_gemm<<<dim3(32,16),256>>>(ph, DD, W1 + (size_t)l*DD*FF_, b1 + l*FF_, nullptr,
                                    nullptr,nullptr,nullptr, pfh, FF_, DD, 1);

        // x = x + ffh@W2 + b2   (last layer writes straight into d_out)
        float* outp = (l == LAYERS-1) ? (float*)d_out : px;
        k_gemm<<<dim3(8,16),256>>>(pfh, FF_, W2 + (size_t)l*FF_*DD, b2 + l*DD, px,
                                    nullptr,nullptr,nullptr, outp, DD, FF_, 0);
    }
}